// round 12
// baseline (speedup 1.0000x reference)
#include <cuda_runtime.h>
#include <cuda_fp16.h>
#include <math.h>
#include <stdint.h>

// ---------------- problem constants ----------------
#define S_LEN   2048
#define BATCH   2
#define HIDDEN  2048
#define NH      16
#define QLORA   1536
#define KVLORA  512
#define DNOPE   128
#define DROPE   64
#define DV      128
#define DQ      192           // DNOPE + DROPE
#define NROWS   (BATCH*S_LEN) // 4096
#define CKV_LD  (KVLORA + DROPE) // 576
#define KV_LD   (NH*(DNOPE+DV))  // 4096
#define Q_LD    (NH*DQ)          // 3072
#define ATTN_LD (NH*DV)          // 2048
#define NFUSE   (QLORA + CKV_LD) // 2112

// ---------------- scratch (device globals; no runtime alloc) ----------------
__device__ __half g_hidh  [(size_t)NROWS*HIDDEN];
__device__ __half g_qaraw [(size_t)NROWS*QLORA];
__device__ __half g_ckvall[(size_t)NROWS*CKV_LD];
__device__ __half g_qah   [(size_t)NROWS*QLORA];
__device__ __half g_ckvh  [(size_t)NROWS*KVLORA];
__device__ __half g_qh    [(size_t)NROWS*Q_LD];
__device__ __half g_kvh   [(size_t)NROWS*KV_LD];
__device__ __half g_vTh   [(size_t)NH*DV*NROWS];
__device__ __half g_kpeh  [(size_t)NROWS*DROPE];
__device__ __half g_attnh [(size_t)NROWS*ATTN_LD];
__device__ __half g_wAT   [(size_t)NFUSE*HIDDEN];
__device__ __half g_wuqT  [(size_t)Q_LD*QLORA];
__device__ __half g_kvbT  [(size_t)KV_LD*KVLORA];
__device__ __half g_owT   [(size_t)HIDDEN*ATTN_LD];

// ---------------- helpers ----------------
#define MMA_F16(acc, a0,a1,a2,a3, b0,b1)                                        \
    asm volatile(                                                               \
        "mma.sync.aligned.m16n8k16.row.col.f32.f16.f16.f32 "                    \
        "{%0,%1,%2,%3}, {%4,%5,%6,%7}, {%8,%9}, {%0,%1,%2,%3};"                 \
        : "+f"(acc[0]), "+f"(acc[1]), "+f"(acc[2]), "+f"(acc[3])                \
        : "r"(a0), "r"(a1), "r"(a2), "r"(a3), "r"(b0), "r"(b1))

#define CP_ASYNC16(dst_u32, src_ptr)                                            \
    asm volatile("cp.async.cg.shared.global [%0], [%1], 16;"                    \
                 :: "r"(dst_u32), "l"(src_ptr))
#define CP_COMMIT() asm volatile("cp.async.commit_group;")
#define CP_WAIT1()  asm volatile("cp.async.wait_group 1;")

__device__ __forceinline__ uint32_t smem_u32(const void* p) {
    uint32_t a;
    asm("{ .reg .u64 t; cvta.to.shared.u64 t, %1; cvt.u32.u64 %0, t; }"
        : "=r"(a) : "l"(p));
    return a;
}

// ---------------- pre-pass kernels ----------------
__global__ void f2h_kernel(const float* __restrict__ src, __half* __restrict__ dst, int n4)
{
    int i = blockIdx.x * 256 + threadIdx.x;
    if (i < n4) {
        float4 v = ((const float4*)src)[i];
        ((__half2*)dst)[2*i]     = __floats2half2_rn(v.x, v.y);
        ((__half2*)dst)[2*i + 1] = __floats2half2_rn(v.z, v.w);
    }
}

// Fused transpose of all 5 weight matrices: src[R][C] fp32 -> dst[C][R] half.
struct TJob { const float* src; __half* dst; int R, C, tile0; };

__global__ __launch_bounds__(256) void transpose5_kernel(TJob j0, TJob j1, TJob j2, TJob j3, TJob j4)
{
    __shared__ float t[32][66];
    const int bid = blockIdx.x;
    TJob j;
    if      (bid < j1.tile0) j = j0;
    else if (bid < j2.tile0) j = j1;
    else if (bid < j3.tile0) j = j2;
    else if (bid < j4.tile0) j = j3;
    else                     j = j4;
    const int t_local = bid - j.tile0;
    const int rtiles  = j.R >> 6;
    const int tr = t_local % rtiles;
    const int tcb = t_local / rtiles;
    const int rbase = tr * 64, cbase = tcb * 32;
    const int tx = threadIdx.x & 31, ty = threadIdx.x >> 5;

#pragma unroll
    for (int it = 0; it < 8; it++) {
        int r = ty + it*8;
        t[tx][r] = j.src[(size_t)(rbase + r)*j.C + cbase + tx];
    }
    __syncthreads();
#pragma unroll
    for (int jj = 0; jj < 4; jj++) {
        int c = ty + jj*8;
        float2 v = *(float2*)&t[c][2*tx];
        *(__half2*)&j.dst[(size_t)(cbase + c)*j.R + rbase + 2*tx] =
            __floats2half2_rn(v.x, v.y);
    }
}

// V slice of kvh -> vT[h][dv][row]
__global__ void vtrans_kernel(const __half* __restrict__ kvh, __half* __restrict__ vT)
{
    __shared__ __half t[32][33];
    const int h   = blockIdx.y >> 2;
    const int dvb = blockIdx.y & 3;
    const int row0 = blockIdx.x * 32;
#pragma unroll
    for (int i = 0; i < 4; i++) {
        int r = row0 + threadIdx.y + i*8;
        t[threadIdx.y + i*8][threadIdx.x] =
            kvh[(size_t)r*KV_LD + h*256 + DNOPE + dvb*32 + threadIdx.x];
    }
    __syncthreads();
#pragma unroll
    for (int i = 0; i < 4; i++) {
        int dv = dvb*32 + threadIdx.y + i*8;
        vT[(size_t)(h*DV + dv)*NROWS + row0 + threadIdx.x] = t[threadIdx.x][threadIdx.y + i*8];
    }
}

// ---------------- fp16 GEMM common tile body ----------------
#define HS 3
#define HBK 64
#define HSTR 72
#define H_TILE_BYTES (128*HSTR*2)
#define H_SMEM (2*HS*H_TILE_BYTES)

// ---------------- single-job fp16 GEMM (split epilogue; used for G1 and out) ----------------
template <typename TOut>
__global__ __launch_bounds__(256, 2) void h16_gemm(
    const __half* __restrict__ A, const __half* __restrict__ Bt,
    TOut* __restrict__ C, int M, int N, int K, int ldc,
    TOut* __restrict__ C2, int ldc2, int nsplit)
{
    extern __shared__ char hsm[];
    const uint32_t smb = smem_u32(hsm);
    const __half* As_h = (const __half*)hsm;
    const __half* Bs_h = (const __half*)(hsm + HS*H_TILE_BYTES);

    const int tid  = threadIdx.x;
    const int lane = tid & 31;
    const int warp = tid >> 5;
    const int wm0  = (warp >> 2) * 64;
    const int wn0  = (warp & 3) * 32;
    const int gr   = lane >> 2;
    const int tc   = lane & 3;

    const int bm = blockIdx.y * 128;
    const int bn = blockIdx.x * 128;

    float acc[4][4][4];
#pragma unroll
    for (int mt = 0; mt < 4; mt++)
#pragma unroll
        for (int nt = 0; nt < 4; nt++)
#pragma unroll
            for (int r = 0; r < 4; r++) acc[mt][nt][r] = 0.0f;

    const int r0 = tid >> 3;
    const int ch = tid & 7;
    const __half* Asrc[4]; const __half* Bsrc[4];
    uint32_t soff[4];
#pragma unroll
    for (int i = 0; i < 4; i++) {
        const int rr = r0 + 32*i;
        Asrc[i] = A + (size_t)(bm + rr)*K + ch*8;
        int nr = bn + rr; if (nr > N-1) nr = N-1;
        Bsrc[i] = Bt + (size_t)nr*K + ch*8;
        soff[i] = (uint32_t)(rr*144 + ch*16);
    }
    const uint32_t a_base = smb;
    const uint32_t b_base = smb + HS*H_TILE_BYTES;

    const int ntiles = K >> 6;

    auto issue_stage = [&](int t) {
        const int kg = t * HBK;
        const uint32_t as = a_base + (t % HS) * H_TILE_BYTES;
        const uint32_t bs = b_base + (t % HS) * H_TILE_BYTES;
#pragma unroll
        for (int i = 0; i < 4; i++) CP_ASYNC16(as + soff[i], Asrc[i] + kg);
#pragma unroll
        for (int i = 0; i < 4; i++) CP_ASYNC16(bs + soff[i], Bsrc[i] + kg);
    };

    issue_stage(0); CP_COMMIT();
    issue_stage(1); CP_COMMIT();

    for (int kt = 0; kt < ntiles; kt++) {
        CP_WAIT1();
        __syncthreads();
        if (kt + 2 < ntiles) issue_stage(kt + 2);
        CP_COMMIT();

        const __half* At  = As_h + (kt % HS) * (128*HSTR);
        const __half* Bts = Bs_h + (kt % HS) * (128*HSTR);
#pragma unroll
        for (int ks = 0; ks < 4; ks++) {
            const int k0 = ks * 16;
            uint32_t af[4][4], bf[4][2];
#pragma unroll
            for (int mt = 0; mt < 4; mt++) {
                const int row = wm0 + mt*16 + gr;
                af[mt][0] = *(const uint32_t*)(At + row*HSTR     + k0 + 2*tc);
                af[mt][1] = *(const uint32_t*)(At + (row+8)*HSTR + k0 + 2*tc);
                af[mt][2] = *(const uint32_t*)(At + row*HSTR     + k0 + 8 + 2*tc);
                af[mt][3] = *(const uint32_t*)(At + (row+8)*HSTR + k0 + 8 + 2*tc);
            }
#pragma unroll
            for (int nt = 0; nt < 4; nt++) {
                const int cr = wn0 + nt*8 + gr;
                bf[nt][0] = *(const uint32_t*)(Bts + cr*HSTR + k0 + 2*tc);
                bf[nt][1] = *(const uint32_t*)(Bts + cr*HSTR + k0 + 8 + 2*tc);
            }
#pragma unroll
            for (int mt = 0; mt < 4; mt++)
#pragma unroll
                for (int nt = 0; nt < 4; nt++)
                    MMA_F16(acc[mt][nt], af[mt][0], af[mt][1], af[mt][2], af[mt][3],
                            bf[nt][0], bf[nt][1]);
        }
    }

#pragma unroll
    for (int mt = 0; mt < 4; mt++) {
        const int row0 = bm + wm0 + mt * 16 + gr;
#pragma unroll
        for (int nt = 0; nt < 4; nt++) {
            const int col = bn + wn0 + nt * 8 + tc * 2;
            if (col >= N) continue;
            TOut* dst;
            size_t idx;
            int ld;
            if (col < nsplit) { dst = C;  ld = ldc;  idx = (size_t)row0*ldc  + col; }
            else              { dst = C2; ld = ldc2; idx = (size_t)row0*ldc2 + (col - nsplit); }
            const size_t idx2 = idx + (size_t)8 * ld;
            if constexpr (sizeof(TOut) == 4) {
                *(float2*)&((float*)dst)[idx]  = make_float2(acc[mt][nt][0], acc[mt][nt][1]);
                *(float2*)&((float*)dst)[idx2] = make_float2(acc[mt][nt][2], acc[mt][nt][3]);
            } else {
                *(__half2*)&((__half*)dst)[idx]  = __floats2half2_rn(acc[mt][nt][0], acc[mt][nt][1]);
                *(__half2*)&((__half*)dst)[idx2] = __floats2half2_rn(acc[mt][nt][2], acc[mt][nt][3]);
            }
        }
    }
}

// ---------------- dual-job persistent fp16 GEMM (half out) ----------------
// Interleaves tiles of two independent GEMMs across a fixed 2-CTA/SM grid to
// kill wave quantization. Tile t < j1.tile0 -> job0, else job1.
struct GJob { const __half* A; const __half* Bt; __half* C; int N, K, ldc, nxt, tile0; };

__global__ __launch_bounds__(256, 2) void h16_gemm_dual(GJob j0, GJob j1, int totalTiles)
{
    extern __shared__ char hsm[];
    const uint32_t smb = smem_u32(hsm);
    const __half* As_h = (const __half*)hsm;
    const __half* Bs_h = (const __half*)(hsm + HS*H_TILE_BYTES);

    const int tid  = threadIdx.x;
    const int lane = tid & 31;
    const int warp = tid >> 5;
    const int wm0  = (warp >> 2) * 64;
    const int wn0  = (warp & 3) * 32;
    const int gr   = lane >> 2;
    const int tc   = lane & 3;
    const int r0 = tid >> 3;
    const int ch = tid & 7;
    uint32_t soff[4];
#pragma unroll
    for (int i = 0; i < 4; i++)
        soff[i] = (uint32_t)((r0 + 32*i)*144 + ch*16);
    const uint32_t a_base = smb;
    const uint32_t b_base = smb + HS*H_TILE_BYTES;

    for (int t = blockIdx.x; t < totalTiles; t += gridDim.x) {
        const bool second = (t >= j1.tile0);
        const GJob j = second ? j1 : j0;
        const int tl = t - (second ? j1.tile0 : 0);
        const int bm = (tl / j.nxt) * 128;
        const int bn = (tl % j.nxt) * 128;
        const int K  = j.K;
        const int ntiles = K >> 6;

        const __half* Asrc[4]; const __half* Bsrc[4];
#pragma unroll
        for (int i = 0; i < 4; i++) {
            const int rr = r0 + 32*i;
            Asrc[i] = j.A + (size_t)(bm + rr)*K + ch*8;
            Bsrc[i] = j.Bt + (size_t)(bn + rr)*K + ch*8;   // N always multiple of 128 here
        }

        float acc[4][4][4];
#pragma unroll
        for (int mt = 0; mt < 4; mt++)
#pragma unroll
            for (int nt = 0; nt < 4; nt++)
#pragma unroll
                for (int r = 0; r < 4; r++) acc[mt][nt][r] = 0.0f;

        auto issue_stage = [&](int s) {
            const int kg = s * HBK;
            const uint32_t as = a_base + (s % HS) * H_TILE_BYTES;
            const uint32_t bs = b_base + (s % HS) * H_TILE_BYTES;
#pragma unroll
            for (int i = 0; i < 4; i++) CP_ASYNC16(as + soff[i], Asrc[i] + kg);
#pragma unroll
            for (int i = 0; i < 4; i++) CP_ASYNC16(bs + soff[i], Bsrc[i] + kg);
        };

        issue_stage(0); CP_COMMIT();
        issue_stage(1); CP_COMMIT();

        for (int kt = 0; kt < ntiles; kt++) {
            CP_WAIT1();
            __syncthreads();
            if (kt + 2 < ntiles) issue_stage(kt + 2);
            CP_COMMIT();

            const __half* At  = As_h + (kt % HS) * (128*HSTR);
            const __half* Bts = Bs_h + (kt % HS) * (128*HSTR);
#pragma unroll
            for (int ks = 0; ks < 4; ks++) {
                const int k0 = ks * 16;
                uint32_t af[4][4], bf[4][2];
#pragma unroll
                for (int mt = 0; mt < 4; mt++) {
                    const int row = wm0 + mt*16 + gr;
                    af[mt][0] = *(const uint32_t*)(At + row*HSTR     + k0 + 2*tc);
                    af[mt][1] = *(const uint32_t*)(At + (row+8)*HSTR + k0 + 2*tc);
                    af[mt][2] = *(const uint32_t*)(At + row*HSTR     + k0 + 8 + 2*tc);
                    af[mt][3] = *(const uint32_t*)(At + (row+8)*HSTR + k0 + 8 + 2*tc);
                }
#pragma unroll
                for (int nt = 0; nt < 4; nt++) {
                    const int cr = wn0 + nt*8 + gr;
                    bf[nt][0] = *(const uint32_t*)(Bts + cr*HSTR + k0 + 2*tc);
                    bf[nt][1] = *(const uint32_t*)(Bts + cr*HSTR + k0 + 8 + 2*tc);
                }
#pragma unroll
                for (int mt = 0; mt < 4; mt++)
#pragma unroll
                    for (int nt = 0; nt < 4; nt++)
                        MMA_F16(acc[mt][nt], af[mt][0], af[mt][1], af[mt][2], af[mt][3],
                                bf[nt][0], bf[nt][1]);
            }
        }

        // epilogue (half)
#pragma unroll
        for (int mt = 0; mt < 4; mt++) {
            const int row0 = bm + wm0 + mt * 16 + gr;
#pragma unroll
            for (int nt = 0; nt < 4; nt++) {
                const int col = bn + wn0 + nt * 8 + tc * 2;
                *(__half2*)&j.C[(size_t)row0*j.ldc + col] =
                    __floats2half2_rn(acc[mt][nt][0], acc[mt][nt][1]);
                *(__half2*)&j.C[(size_t)(row0 + 8)*j.ldc + col] =
                    __floats2half2_rn(acc[mt][nt][2], acc[mt][nt][3]);
            }
        }
        __syncthreads();   // protect smem reuse by next tile
    }
}

// ---------------- fused RMSNorm(qa) + RMSNorm(ckv) + RoPE(k_pe) ----------------
__global__ void normfuse_kernel(const __half* __restrict__ qaraw,
                                const __half* __restrict__ ckvall,
                                const float* __restrict__ q_ln,
                                const float* __restrict__ kv_ln,
                                __half* __restrict__ qah,
                                __half* __restrict__ ckvh,
                                __half* __restrict__ kpeh)
{
    __shared__ float red1[256], red2[256];
    const int row = blockIdx.x;
    const int tid = threadIdx.x;
    const __half* p1 = qaraw + (size_t)row*QLORA;
    const __half* p2 = ckvall + (size_t)row*CKV_LD;

    float ss1 = 0.f;
    for (int c = tid; c < QLORA/2; c += 256) {
        float2 v = __half22float2(((const __half2*)p1)[c]);
        ss1 += v.x*v.x + v.y*v.y;
    }
    float ss2 = 0.f;
    {   // KVLORA/2 = 256: exactly one element per thread
        float2 v = __half22float2(((const __half2*)p2)[tid]);
        ss2 = v.x*v.x + v.y*v.y;
    }
    red1[tid] = ss1; red2[tid] = ss2;
    __syncthreads();
    for (int s = 128; s; s >>= 1) {
        if (tid < s) { red1[tid] += red1[tid + s]; red2[tid] += red2[tid + s]; }
        __syncthreads();
    }
    const float sc1 = rsqrtf(red1[0] / (float)QLORA  + 1e-6f);
    const float sc2 = rsqrtf(red2[0] / (float)KVLORA + 1e-6f);

    __half* d1 = qah  + (size_t)row*QLORA;
    __half* d2 = ckvh + (size_t)row*KVLORA;
    for (int c = tid; c < QLORA; c += 256)
        d1[c] = __float2half_rn(__half2float(p1[c]) * sc1 * q_ln[c]);
    for (int c = tid; c < KVLORA; c += 256)
        d2[c] = __float2half_rn(__half2float(p2[c]) * sc2 * kv_ln[c]);

    if (tid < 32) {
        const int lane = tid;
        const __half* base = p2 + KVLORA;
        float xe = __half2float(base[2*lane]), xo = __half2float(base[2*lane + 1]);
        float inv = 1.0f / powf(10000.0f, (2.0f * (float)lane) / 64.0f);
        float ph = (float)(row % S_LEN) * inv;
        float sn, cs;
        sincosf(ph, &sn, &cs);
        kpeh[(size_t)row*DROPE + lane]      = __float2half_rn(xe*cs - xo*sn);
        kpeh[(size_t)row*DROPE + lane + 32] = __float2half_rn(xo*cs + xe*sn);
    }
}

// ---------------- RoPE q ----------------
__global__ void rope_q_h_kernel(__half* __restrict__ q)
{
    const int row = blockIdx.x;
    const int h = threadIdx.x >> 5, lane = threadIdx.x & 31;
    __half* base = q + (size_t)row*Q_LD + h*DQ + DNOPE;
    float xe = __half2float(base[2*lane]), xo = __half2float(base[2*lane + 1]);
    float inv = 1.0f / powf(10000.0f, (2.0f * (float)lane) / 64.0f);
    float ph = (float)(row % S_LEN) * inv;
    float sn, cs;
    sincosf(ph, &sn, &cs);
    __syncwarp();
    base[lane]      = __float2half_rn(xe*cs - xo*sn);
    base[lane + 32] = __float2half_rn(xo*cs + xe*sn);
}

// ---------------- all-fp16 tensor-core causal flash attention ----------------
#define FQH 200
#define FVH 40
#define FPH 40
#define BR 128
#define BC 32
#define FLASH_SMEM ((BR*FQH + 2*BC*FQH + 2*DV*FVH + BR*FPH)*2)

__global__ __launch_bounds__(256, 2) void flash_h_kernel(
    const __half* __restrict__ q, const __half* __restrict__ kvh,
    const __half* __restrict__ vT, const __half* __restrict__ kpeh,
    __half* __restrict__ attn)
{
    extern __shared__ __half smh[];
    __half* Qs = smh;
    __half* Ks = Qs + BR*FQH;
    __half* Vt = Ks + 2*BC*FQH;
    __half* Ps = Vt + 2*DV*FVH;

    const int tid  = threadIdx.x;
    const int lane = tid & 31;
    const int warp = tid >> 5;
    const int gr   = lane >> 2;
    const int tc   = lane & 3;
    const int qt = (gridDim.x - 1) - blockIdx.x;
    const int b  = blockIdx.y >> 4;
    const int h  = blockIdx.y & 15;
    const float scale = 0.07216878364870323f; // 1/sqrt(192)

    const int qrow0 = b*S_LEN + qt*BR;
    const int wr0   = warp * 16;

    uint32_t ksm[2], vsm[2];
    ksm[0] = smem_u32(Ks);
    ksm[1] = smem_u32(Ks + BC*FQH);
    vsm[0] = smem_u32(Vt);
    vsm[1] = smem_u32(Vt + DV*FVH);

#pragma unroll
    for (int t = 0; t < 12; t++) {
        int idx = tid + t*256;
        int r = idx / 24, c = idx % 24;
        *(uint4*)&Qs[r*FQH + c*8] =
            *(const uint4*)(q + (size_t)(qrow0 + r)*Q_LD + h*DQ + c*8);
    }

    float m0 = -INFINITY, m1 = -INFINITY, l0 = 0.f, l1 = 0.f;
    float o[16][4];
#pragma unroll
    for (int nt = 0; nt < 16; nt++)
#pragma unroll
        for (int r = 0; r < 4; r++) o[nt][r] = 0.f;

    const int jmax = 4*qt + 3;

    auto issue_tile = [&](int j, int buf) {
        const int krow0 = b*S_LEN + j*BC;
#pragma unroll
        for (int t = 0; t < 3; t++) {
            int idx = tid + t*256;
            int r = idx / 24, col8 = (idx % 24) * 8;
            const __half* src = (col8 < DNOPE)
                ? kvh + (size_t)(krow0 + r)*KV_LD + h*256 + col8
                : kpeh + (size_t)(krow0 + r)*DROPE + (col8 - DNOPE);
            CP_ASYNC16(ksm[buf] + (uint32_t)(r*FQH + col8)*2, src);
        }
#pragma unroll
        for (int t = 0; t < 2; t++) {
            int idx = tid + t*256;
            int r = idx >> 2, c8 = (idx & 3) * 8;
            const __half* src = vT + (size_t)(h*DV + r)*NROWS + krow0 + c8;
            CP_ASYNC16(vsm[buf] + (uint32_t)(r*FVH + c8)*2, src);
        }
    };

    issue_tile(0, 0);
    CP_COMMIT();

    for (int j = 0; j <= jmax; j++) {
        __syncthreads();
        if (j + 1 <= jmax) issue_tile(j + 1, (j + 1) & 1);
        CP_COMMIT();
        CP_WAIT1();
        __syncthreads();

        const int off = j*BC - qt*BR;
        if (off > wr0 + 15) continue;
        const bool needMask = (off + BC - 1 > wr0);

        const __half* Ksb = Ks + (j & 1)*BC*FQH;
        const __half* Vtb = Vt + (j & 1)*DV*FVH;

        float accS[4][4];
#pragma unroll
        for (int nt = 0; nt < 4; nt++)
#pragma unroll
            for (int r = 0; r < 4; r++) accS[nt][r] = 0.f;

#pragma unroll
        for (int k = 0; k < 12; k++) {
            const int k0 = k * 16;
            uint32_t a0 = *(const uint32_t*)(Qs + (wr0 + gr)*FQH     + k0 + 2*tc);
            uint32_t a1 = *(const uint32_t*)(Qs + (wr0 + gr + 8)*FQH + k0 + 2*tc);
            uint32_t a2 = *(const uint32_t*)(Qs + (wr0 + gr)*FQH     + k0 + 8 + 2*tc);
            uint32_t a3 = *(const uint32_t*)(Qs + (wr0 + gr + 8)*FQH + k0 + 8 + 2*tc);
#pragma unroll
            for (int nt = 0; nt < 4; nt++) {
                uint32_t b0 = *(const uint32_t*)(Ksb + (nt*8 + gr)*FQH + k0 + 2*tc);
                uint32_t b1 = *(const uint32_t*)(Ksb + (nt*8 + gr)*FQH + k0 + 8 + 2*tc);
                MMA_F16(accS[nt], a0, a1, a2, a3, b0, b1);
            }
        }

        if (needMask) {
            const int r0 = wr0 + gr, r1 = r0 + 8;
#pragma unroll
            for (int nt = 0; nt < 4; nt++) {
                const int c0 = nt*8 + 2*tc + off;
                accS[nt][0] = (c0     <= r0) ? accS[nt][0]*scale : -INFINITY;
                accS[nt][1] = (c0 + 1 <= r0) ? accS[nt][1]*scale : -INFINITY;
                accS[nt][2] = (c0     <= r1) ? accS[nt][2]*scale : -INFINITY;
                accS[nt][3] = (c0 + 1 <= r1) ? accS[nt][3]*scale : -INFINITY;
            }
        } else {
#pragma unroll
            for (int nt = 0; nt < 4; nt++)
#pragma unroll
                for (int r = 0; r < 4; r++) accS[nt][r] *= scale;
        }

        float rm0 = -INFINITY, rm1 = -INFINITY;
#pragma unroll
        for (int nt = 0; nt < 4; nt++) {
            rm0 = fmaxf(rm0, fmaxf(accS[nt][0], accS[nt][1]));
            rm1 = fmaxf(rm1, fmaxf(accS[nt][2], accS[nt][3]));
        }
        rm0 = fmaxf(rm0, __shfl_xor_sync(0xffffffffu, rm0, 1));
        rm0 = fmaxf(rm0, __shfl_xor_sync(0xffffffffu, rm0, 2));
        rm1 = fmaxf(rm1, __shfl_xor_sync(0xffffffffu, rm1, 1));
        rm1 = fmaxf(rm1, __shfl_xor_sync(0xffffffffu, rm1, 2));

        const float mn0 = fmaxf(m0, rm0), mn1 = fmaxf(m1, rm1);
        const float al0 = __expf(m0 - mn0), al1 = __expf(m1 - mn1);
        m0 = mn0; m1 = mn1;

        float rs0 = 0.f, rs1 = 0.f;
#pragma unroll
        for (int nt = 0; nt < 4; nt++) {
            float p0 = __expf(accS[nt][0] - mn0);
            float p1 = __expf(accS[nt][1] - mn0);
            float p2 = __expf(accS[nt][2] - mn1);
            float p3 = __expf(accS[nt][3] - mn1);
            rs0 += p0 + p1; rs1 += p2 + p3;
            const int c0 = nt*8 + 2*tc;
            *(__half2*)&Ps[(wr0 + gr)*FPH + c0]     = __floats2half2_rn(p0, p1);
            *(__half2*)&Ps[(wr0 + gr + 8)*FPH + c0] = __floats2half2_rn(p2, p3);
        }
        rs0 += __shfl_xor_sync(0xffffffffu, rs0, 1);
        rs0 += __shfl_xor_sync(0xffffffffu, rs0, 2);
        rs1 += __shfl_xor_sync(0xffffffffu, rs1, 1);
        rs1 += __shfl_xor_sync(0xffffffffu, rs1, 2);
        l0 = l0*al0 + rs0;
        l1 = l1*al1 + rs1;

#pragma unroll
        for (int nt = 0; nt < 16; nt++) {
            o[nt][0] *= al0; o[nt][1] *= al0;
            o[nt][2] *= al1; o[nt][3] *= al1;
        }
        __syncwarp();

#pragma unroll
        for (int k = 0; k < 2; k++) {
            const int k0 = k * 16;
            uint32_t a0 = *(const uint32_t*)(Ps + (wr0 + gr)*FPH     + k0 + 2*tc);
            uint32_t a1 = *(const uint32_t*)(Ps + (wr0 + gr + 8)*FPH + k0 + 2*tc);
            uint32_t a2 = *(const uint32_t*)(Ps + (wr0 + gr)*FPH     + k0 + 8 + 2*tc);
            uint32_t a3 = *(const uint32_t*)(Ps + (wr0 + gr + 8)*FPH + k0 + 8 + 2*tc);
#pragma unroll
            for (int nt = 0; nt < 16; nt++) {
                uint32_t b0 = *(const uint32_t*)(Vtb + (nt*8 + gr)*FVH + k0 + 2*tc);
                uint32_t b1 = *(const uint32_t*)(Vtb + (nt*8 + gr)*FVH + k0 + 8 + 2*tc);
                MMA_F16(o[nt], a0, a1, a2, a3, b0, b1);
            }
        }
    }

    const float il0 = 1.0f / l0, il1 = 1.0f / l1;
    const int row0 = qrow0 + wr0 + gr;
#pragma unroll
    for (int nt = 0; nt < 16; nt++) {
        const int col = h*DV + nt*8 + 2*tc;
        *(__half2*)&attn[(size_t)row0*ATTN_LD + col] =
            __floats2half2_rn(o[nt][0]*il0, o[nt][1]*il0);
        *(__half2*)&attn[(size_t)(row0 + 8)*ATTN_LD + col] =
            __floats2half2_rn(o[nt][2]*il1, o[nt][3]*il1);
    }
}

// ---------------- launch ----------------
extern "C" void kernel_launch(void* const* d_in, const int* in_sizes, int n_in,
                              void* d_out, int out_size)
{
    const float* hid    = (const float*)d_in[0];
    const float* w_dq   = (const float*)d_in[1];
    const float* q_ln   = (const float*)d_in[2];
    const float* w_uq   = (const float*)d_in[3];
    const float* kv_a_w = (const float*)d_in[4];
    const float* kv_ln  = (const float*)d_in[5];
    const float* kv_b_w = (const float*)d_in[6];
    const float* o_w    = (const float*)d_in[7];
    float* out = (float*)d_out;

    __half *hidh, *qaraw, *ckvall, *qah, *ckvh, *qh, *kvh, *vTh, *kpeh, *attnh;
    __half *wAT, *wuqT, *kvbT, *owT;
    cudaGetSymbolAddress((void**)&hidh,  g_hidh);
    cudaGetSymbolAddress((void**)&qaraw, g_qaraw);
    cudaGetSymbolAddress((void**)&ckvall,g_ckvall);
    cudaGetSymbolAddress((void**)&qah,   g_qah);
    cudaGetSymbolAddress((void**)&ckvh,  g_ckvh);
    cudaGetSymbolAddress((void**)&qh,    g_qh);
    cudaGetSymbolAddress((void**)&kvh,   g_kvh);
    cudaGetSymbolAddress((void**)&vTh,   g_vTh);
    cudaGetSymbolAddress((void**)&kpeh,  g_kpeh);
    cudaGetSymbolAddress((void**)&attnh, g_attnh);
    cudaGetSymbolAddress((void**)&wAT,   g_wAT);
    cudaGetSymbolAddress((void**)&wuqT,  g_wuqT);
    cudaGetSymbolAddress((void**)&kvbT,  g_kvbT);
    cudaGetSymbolAddress((void**)&owT,   g_owT);

    cudaFuncSetAttribute(flash_h_kernel, cudaFuncAttributeMaxDynamicSharedMemorySize, FLASH_SMEM);
    cudaFuncSetAttribute(h16_gemm<float>, cudaFuncAttributeMaxDynamicSharedMemorySize, H_SMEM);
    cudaFuncSetAttribute(h16_gemm<__half>, cudaFuncAttributeMaxDynamicSharedMemorySize, H_SMEM);
    cudaFuncSetAttribute(h16_gemm_dual, cudaFuncAttributeMaxDynamicSharedMemorySize, H_SMEM);

    // pre-pass: hidden -> half; all weight transposes fused in one launch
    f2h_kernel<<<(NROWS*HIDDEN/4 + 255)/256, 256>>>(hid, hidh, NROWS*HIDDEN/4);
    {
        TJob j0 = { w_dq,   wAT,                          HIDDEN, QLORA,  0 };
        int t0 = (HIDDEN/64)*(QLORA/32);
        TJob j1 = { kv_a_w, wAT + (size_t)QLORA*HIDDEN,   HIDDEN, CKV_LD, t0 };
        int t1 = t0 + (HIDDEN/64)*(CKV_LD/32);
        TJob j2 = { w_uq,   wuqT,                         QLORA,  Q_LD,   t1 };
        int t2 = t1 + (QLORA/64)*(Q_LD/32);
        TJob j3 = { kv_b_w, kvbT,                         KVLORA, KV_LD,  t2 };
        int t3 = t2 + (KVLORA/64)*(KV_LD/32);
        TJob j4 = { o_w,    owT,                          ATTN_LD, HIDDEN, t3 };
        int t4 = t3 + (ATTN_LD/64)*(HIDDEN/32);
        transpose5_kernel<<<t4, 256>>>(j0, j1, j2, j3, j4);
    }

    // fused [q_a | ckv_pe] = hidden @ [w_dq | kv_a_w]  [4096, 2112] k=2048 (half, split)
    h16_gemm<__half><<<dim3((NFUSE+127)/128, NROWS/128), 256, H_SMEM>>>(
        hidh, wAT, qaraw, NROWS, NFUSE, HIDDEN, QLORA, ckvall, CKV_LD, QLORA);
    // fused RMSNorm(qa) + RMSNorm(ckv) + RoPE(k_pe)
    normfuse_kernel<<<NROWS, 256>>>(qaraw, ckvall, q_ln, kv_ln, qah, ckvh, kpeh);
    // dual persistent GEMM:  q = qah @ wuq  ||  kv = ckvh @ kvb
    {
        GJob ja = { qah,  wuqT, qh,  Q_LD,  QLORA,  Q_LD,  Q_LD/128,  0 };
        int ta = (Q_LD/128) * (NROWS/128);      // 768 tiles
        GJob jb = { ckvh, kvbT, kvh, KV_LD, KVLORA, KV_LD, KV_LD/128, ta };
        int total = ta + (KV_LD/128) * (NROWS/128);  // +1024
        h16_gemm_dual<<<296, 256, H_SMEM>>>(ja, jb, total);
    }
    // RoPE q_pe in place on half q
    rope_q_h_kernel<<<NROWS, 512>>>(qh);
    // V transpose: kvh -> vT[h][dv][row]
    vtrans_kernel<<<dim3(NROWS/32, NH*4), dim3(32,8)>>>(kvh, vTh);
    // all-fp16 causal flash attention -> attnh
    flash_h_kernel<<<dim3(S_LEN/BR, BATCH*NH), 256, FLASH_SMEM>>>(qh, kvh, vTh, kpeh, attnh);
    // out = attn @ o_w  [4096,2048] k=2048 (fp32 out)
    h16_gemm<float><<<dim3(HIDDEN/128, NROWS/128), 256, H_SMEM>>>(
        attnh, owT, out, NROWS, HIDDEN, ATTN_LD, HIDDEN, (float*)nullptr, 0, 1<<30);
}

// round 13
// speedup vs baseline: 1.0413x; 1.0413x over previous
#include <cuda_runtime.h>
#include <cuda_fp16.h>
#include <math.h>
#include <stdint.h>

// ---------------- problem constants ----------------
#define S_LEN   2048
#define BATCH   2
#define HIDDEN  2048
#define NH      16
#define QLORA   1536
#define KVLORA  512
#define DNOPE   128
#define DROPE   64
#define DV      128
#define DQ      192           // DNOPE + DROPE
#define NROWS   (BATCH*S_LEN) // 4096
#define CKV_LD  (KVLORA + DROPE) // 576
#define KV_LD   (NH*(DNOPE+DV))  // 4096
#define Q_LD    (NH*DQ)          // 3072
#define ATTN_LD (NH*DV)          // 2048
#define NFUSE   (QLORA + CKV_LD) // 2112

// ---------------- scratch (device globals; no runtime alloc) ----------------
__device__ __half g_hidh  [(size_t)NROWS*HIDDEN];
__device__ __half g_qaraw [(size_t)NROWS*QLORA];
__device__ __half g_ckvall[(size_t)NROWS*CKV_LD];
__device__ __half g_qah   [(size_t)NROWS*QLORA];
__device__ __half g_ckvh  [(size_t)NROWS*KVLORA];
__device__ __half g_qh    [(size_t)NROWS*Q_LD];     // q (half, UN-roped; rope in flash)
__device__ __half g_kvh   [(size_t)NROWS*KV_LD];
__device__ __half g_vTh   [(size_t)NH*DV*NROWS];
__device__ __half g_kpeh  [(size_t)NROWS*DROPE];
__device__ __half g_attnh [(size_t)NROWS*ATTN_LD];
__device__ __half g_wAT   [(size_t)NFUSE*HIDDEN];
__device__ __half g_wuqT  [(size_t)Q_LD*QLORA];
__device__ __half g_kvbT  [(size_t)KV_LD*KVLORA];
__device__ __half g_owT   [(size_t)HIDDEN*ATTN_LD];

// ---------------- helpers ----------------
#define MMA_F16(acc, a0,a1,a2,a3, b0,b1)                                        \
    asm volatile(                                                               \
        "mma.sync.aligned.m16n8k16.row.col.f32.f16.f16.f32 "                    \
        "{%0,%1,%2,%3}, {%4,%5,%6,%7}, {%8,%9}, {%0,%1,%2,%3};"                 \
        : "+f"(acc[0]), "+f"(acc[1]), "+f"(acc[2]), "+f"(acc[3])                \
        : "r"(a0), "r"(a1), "r"(a2), "r"(a3), "r"(b0), "r"(b1))

#define CP_ASYNC16(dst_u32, src_ptr)                                            \
    asm volatile("cp.async.cg.shared.global [%0], [%1], 16;"                    \
                 :: "r"(dst_u32), "l"(src_ptr))
#define CP_COMMIT() asm volatile("cp.async.commit_group;")
#define CP_WAIT1()  asm volatile("cp.async.wait_group 1;")

__device__ __forceinline__ uint32_t smem_u32(const void* p) {
    uint32_t a;
    asm("{ .reg .u64 t; cvta.to.shared.u64 t, %1; cvt.u32.u64 %0, t; }"
        : "=r"(a) : "l"(p));
    return a;
}

// ---------------- pre-pass kernels ----------------
__global__ void f2h_kernel(const float* __restrict__ src, __half* __restrict__ dst, int n4)
{
    int i = blockIdx.x * 256 + threadIdx.x;
    if (i < n4) {
        float4 v = ((const float4*)src)[i];
        ((__half2*)dst)[2*i]     = __floats2half2_rn(v.x, v.y);
        ((__half2*)dst)[2*i + 1] = __floats2half2_rn(v.z, v.w);
    }
}

// Fused transpose of all 5 weight matrices: src[R][C] fp32 -> dst[C][R] half.
struct TJob { const float* src; __half* dst; int R, C, tile0; };

__global__ __launch_bounds__(256) void transpose5_kernel(TJob j0, TJob j1, TJob j2, TJob j3, TJob j4)
{
    __shared__ float t[32][66];
    const int bid = blockIdx.x;
    TJob j;
    if      (bid < j1.tile0) j = j0;
    else if (bid < j2.tile0) j = j1;
    else if (bid < j3.tile0) j = j2;
    else if (bid < j4.tile0) j = j3;
    else                     j = j4;
    const int t_local = bid - j.tile0;
    const int rtiles  = j.R >> 6;
    const int tr = t_local % rtiles;
    const int tcb = t_local / rtiles;
    const int rbase = tr * 64, cbase = tcb * 32;
    const int tx = threadIdx.x & 31, ty = threadIdx.x >> 5;

#pragma unroll
    for (int it = 0; it < 8; it++) {
        int r = ty + it*8;
        t[tx][r] = j.src[(size_t)(rbase + r)*j.C + cbase + tx];
    }
    __syncthreads();
#pragma unroll
    for (int jj = 0; jj < 4; jj++) {
        int c = ty + jj*8;
        float2 v = *(float2*)&t[c][2*tx];
        *(__half2*)&j.dst[(size_t)(cbase + c)*j.R + rbase + 2*tx] =
            __floats2half2_rn(v.x, v.y);
    }
}

// V slice of kvh -> vT[h][dv][row]
__global__ void vtrans_kernel(const __half* __restrict__ kvh, __half* __restrict__ vT)
{
    __shared__ __half t[32][33];
    const int h   = blockIdx.y >> 2;
    const int dvb = blockIdx.y & 3;
    const int row0 = blockIdx.x * 32;
#pragma unroll
    for (int i = 0; i < 4; i++) {
        int r = row0 + threadIdx.y + i*8;
        t[threadIdx.y + i*8][threadIdx.x] =
            kvh[(size_t)r*KV_LD + h*256 + DNOPE + dvb*32 + threadIdx.x];
    }
    __syncthreads();
#pragma unroll
    for (int i = 0; i < 4; i++) {
        int dv = dvb*32 + threadIdx.y + i*8;
        vT[(size_t)(h*DV + dv)*NROWS + row0 + threadIdx.x] = t[threadIdx.x][threadIdx.y + i*8];
    }
}

// ---------------- fp16 tensor-core GEMM (templated output, split epilogue) ----------------
#define HS 3
#define HBK 64
#define HSTR 72
#define H_TILE_BYTES (128*HSTR*2)
#define H_SMEM (2*HS*H_TILE_BYTES)

template <typename TOut>
__global__ __launch_bounds__(256, 2) void h16_gemm(
    const __half* __restrict__ A, const __half* __restrict__ Bt,
    TOut* __restrict__ C, int M, int N, int K, int ldc,
    TOut* __restrict__ C2, int ldc2, int nsplit)
{
    extern __shared__ char hsm[];
    const uint32_t smb = smem_u32(hsm);
    const __half* As_h = (const __half*)hsm;
    const __half* Bs_h = (const __half*)(hsm + HS*H_TILE_BYTES);

    const int tid  = threadIdx.x;
    const int lane = tid & 31;
    const int warp = tid >> 5;
    const int wm0  = (warp >> 2) * 64;
    const int wn0  = (warp & 3) * 32;
    const int gr   = lane >> 2;
    const int tc   = lane & 3;

    const int bm = blockIdx.y * 128;
    const int bn = blockIdx.x * 128;

    float acc[4][4][4];
#pragma unroll
    for (int mt = 0; mt < 4; mt++)
#pragma unroll
        for (int nt = 0; nt < 4; nt++)
#pragma unroll
            for (int r = 0; r < 4; r++) acc[mt][nt][r] = 0.0f;

    const int r0 = tid >> 3;
    const int ch = tid & 7;
    const __half* Asrc[4]; const __half* Bsrc[4];
    uint32_t soff[4];
#pragma unroll
    for (int i = 0; i < 4; i++) {
        const int rr = r0 + 32*i;
        Asrc[i] = A + (size_t)(bm + rr)*K + ch*8;
        int nr = bn + rr; if (nr > N-1) nr = N-1;
        Bsrc[i] = Bt + (size_t)nr*K + ch*8;
        soff[i] = (uint32_t)(rr*144 + ch*16);
    }
    const uint32_t a_base = smb;
    const uint32_t b_base = smb + HS*H_TILE_BYTES;

    const int ntiles = K >> 6;

    auto issue_stage = [&](int t) {
        const int kg = t * HBK;
        const uint32_t as = a_base + (t % HS) * H_TILE_BYTES;
        const uint32_t bs = b_base + (t % HS) * H_TILE_BYTES;
#pragma unroll
        for (int i = 0; i < 4; i++) CP_ASYNC16(as + soff[i], Asrc[i] + kg);
#pragma unroll
        for (int i = 0; i < 4; i++) CP_ASYNC16(bs + soff[i], Bsrc[i] + kg);
    };

    issue_stage(0); CP_COMMIT();
    issue_stage(1); CP_COMMIT();

    for (int kt = 0; kt < ntiles; kt++) {
        CP_WAIT1();
        __syncthreads();
        if (kt + 2 < ntiles) issue_stage(kt + 2);
        CP_COMMIT();

        const __half* At  = As_h + (kt % HS) * (128*HSTR);
        const __half* Bts = Bs_h + (kt % HS) * (128*HSTR);
#pragma unroll
        for (int ks = 0; ks < 4; ks++) {
            const int k0 = ks * 16;
            uint32_t af[4][4], bf[4][2];
#pragma unroll
            for (int mt = 0; mt < 4; mt++) {
                const int row = wm0 + mt*16 + gr;
                af[mt][0] = *(const uint32_t*)(At + row*HSTR     + k0 + 2*tc);
                af[mt][1] = *(const uint32_t*)(At + (row+8)*HSTR + k0 + 2*tc);
                af[mt][2] = *(const uint32_t*)(At + row*HSTR     + k0 + 8 + 2*tc);
                af[mt][3] = *(const uint32_t*)(At + (row+8)*HSTR + k0 + 8 + 2*tc);
            }
#pragma unroll
            for (int nt = 0; nt < 4; nt++) {
                const int cr = wn0 + nt*8 + gr;
                bf[nt][0] = *(const uint32_t*)(Bts + cr*HSTR + k0 + 2*tc);
                bf[nt][1] = *(const uint32_t*)(Bts + cr*HSTR + k0 + 8 + 2*tc);
            }
#pragma unroll
            for (int mt = 0; mt < 4; mt++)
#pragma unroll
                for (int nt = 0; nt < 4; nt++)
                    MMA_F16(acc[mt][nt], af[mt][0], af[mt][1], af[mt][2], af[mt][3],
                            bf[nt][0], bf[nt][1]);
        }
    }

#pragma unroll
    for (int mt = 0; mt < 4; mt++) {
        const int row0 = bm + wm0 + mt * 16 + gr;
#pragma unroll
        for (int nt = 0; nt < 4; nt++) {
            const int col = bn + wn0 + nt * 8 + tc * 2;
            if (col >= N) continue;
            TOut* dst;
            size_t idx;
            int ld;
            if (col < nsplit) { dst = C;  ld = ldc;  idx = (size_t)row0*ldc  + col; }
            else              { dst = C2; ld = ldc2; idx = (size_t)row0*ldc2 + (col - nsplit); }
            const size_t idx2 = idx + (size_t)8 * ld;
            if constexpr (sizeof(TOut) == 4) {
                *(float2*)&((float*)dst)[idx]  = make_float2(acc[mt][nt][0], acc[mt][nt][1]);
                *(float2*)&((float*)dst)[idx2] = make_float2(acc[mt][nt][2], acc[mt][nt][3]);
            } else {
                *(__half2*)&((__half*)dst)[idx]  = __floats2half2_rn(acc[mt][nt][0], acc[mt][nt][1]);
                *(__half2*)&((__half*)dst)[idx2] = __floats2half2_rn(acc[mt][nt][2], acc[mt][nt][3]);
            }
        }
    }
}

// ---------------- fused RMSNorm(qa) + RMSNorm(ckv) + RoPE(k_pe) ----------------
__global__ void normfuse_kernel(const __half* __restrict__ qaraw,
                                const __half* __restrict__ ckvall,
                                const float* __restrict__ q_ln,
                                const float* __restrict__ kv_ln,
                                __half* __restrict__ qah,
                                __half* __restrict__ ckvh,
                                __half* __restrict__ kpeh)
{
    __shared__ float red1[256], red2[256];
    const int row = blockIdx.x;
    const int tid = threadIdx.x;
    const __half* p1 = qaraw + (size_t)row*QLORA;
    const __half* p2 = ckvall + (size_t)row*CKV_LD;

    float ss1 = 0.f;
    for (int c = tid; c < QLORA/2; c += 256) {
        float2 v = __half22float2(((const __half2*)p1)[c]);
        ss1 += v.x*v.x + v.y*v.y;
    }
    float ss2 = 0.f;
    {
        float2 v = __half22float2(((const __half2*)p2)[tid]);
        ss2 = v.x*v.x + v.y*v.y;
    }
    red1[tid] = ss1; red2[tid] = ss2;
    __syncthreads();
    for (int s = 128; s; s >>= 1) {
        if (tid < s) { red1[tid] += red1[tid + s]; red2[tid] += red2[tid + s]; }
        __syncthreads();
    }
    const float sc1 = rsqrtf(red1[0] / (float)QLORA  + 1e-6f);
    const float sc2 = rsqrtf(red2[0] / (float)KVLORA + 1e-6f);

    __half* d1 = qah  + (size_t)row*QLORA;
    __half* d2 = ckvh + (size_t)row*KVLORA;
    for (int c = tid; c < QLORA; c += 256)
        d1[c] = __float2half_rn(__half2float(p1[c]) * sc1 * q_ln[c]);
    for (int c = tid; c < KVLORA; c += 256)
        d2[c] = __float2half_rn(__half2float(p2[c]) * sc2 * kv_ln[c]);

    if (tid < 32) {
        const int lane = tid;
        const __half* base = p2 + KVLORA;
        float xe = __half2float(base[2*lane]), xo = __half2float(base[2*lane + 1]);
        float inv = 1.0f / powf(10000.0f, (2.0f * (float)lane) / 64.0f);
        float ph = (float)(row % S_LEN) * inv;
        float sn, cs;
        sincosf(ph, &sn, &cs);
        kpeh[(size_t)row*DROPE + lane]      = __float2half_rn(xe*cs - xo*sn);
        kpeh[(size_t)row*DROPE + lane + 32] = __float2half_rn(xo*cs + xe*sn);
    }
}

// ---------------- all-fp16 tensor-core causal flash attention (q-RoPE fused) ----------------
#define FQH 200
#define FVH 40
#define FPH 40
#define BR 128
#define BC 32
#define FLASH_SMEM ((BR*FQH + 2*BC*FQH + 2*DV*FVH + BR*FPH)*2)

__global__ __launch_bounds__(256, 2) void flash_h_kernel(
    const __half* __restrict__ q, const __half* __restrict__ kvh,
    const __half* __restrict__ vT, const __half* __restrict__ kpeh,
    __half* __restrict__ attn)
{
    extern __shared__ __half smh[];
    __half* Qs = smh;
    __half* Ks = Qs + BR*FQH;
    __half* Vt = Ks + 2*BC*FQH;
    __half* Ps = Vt + 2*DV*FVH;

    const int tid  = threadIdx.x;
    const int lane = tid & 31;
    const int warp = tid >> 5;
    const int gr   = lane >> 2;
    const int tc   = lane & 3;
    const int qt = (gridDim.x - 1) - blockIdx.x;
    const int b  = blockIdx.y >> 4;
    const int h  = blockIdx.y & 15;
    const float scale = 0.07216878364870323f; // 1/sqrt(192)

    const int qrow0 = b*S_LEN + qt*BR;
    const int wr0   = warp * 16;

    uint32_t ksm[2], vsm[2];
    ksm[0] = smem_u32(Ks);
    ksm[1] = smem_u32(Ks + BC*FQH);
    vsm[0] = smem_u32(Vt);
    vsm[1] = smem_u32(Vt + DV*FVH);

    const int jmax = 4*qt + 3;

    auto issue_tile = [&](int j, int buf) {
        const int krow0 = b*S_LEN + j*BC;
#pragma unroll
        for (int t = 0; t < 3; t++) {
            int idx = tid + t*256;
            int r = idx / 24, col8 = (idx % 24) * 8;
            const __half* src = (col8 < DNOPE)
                ? kvh + (size_t)(krow0 + r)*KV_LD + h*256 + col8
                : kpeh + (size_t)(krow0 + r)*DROPE + (col8 - DNOPE);
            CP_ASYNC16(ksm[buf] + (uint32_t)(r*FQH + col8)*2, src);
        }
#pragma unroll
        for (int t = 0; t < 2; t++) {
            int idx = tid + t*256;
            int r = idx >> 2, c8 = (idx & 3) * 8;
            const __half* src = vT + (size_t)(h*DV + r)*NROWS + krow0 + c8;
            CP_ASYNC16(vsm[buf] + (uint32_t)(r*FVH + c8)*2, src);
        }
    };

    // issue tile 0 first so K/V loads overlap Q staging + rope
    issue_tile(0, 0);
    CP_COMMIT();

    // load Q tile (128 x 192 halves), raw (un-roped)
#pragma unroll
    for (int t = 0; t < 12; t++) {
        int idx = tid + t*256;
        int r = idx / 24, c = idx % 24;
        *(uint4*)&Qs[r*FQH + c*8] =
            *(const uint4*)(q + (size_t)(qrow0 + r)*Q_LD + h*DQ + c*8);
    }
    __syncthreads();

    // apply q-RoPE in smem: warp w handles rows {8it + w}, lane = pair index
    {
        const float inv = 1.0f / powf(10000.0f, (2.0f * (float)lane) / 64.0f);
#pragma unroll
        for (int it = 0; it < 16; it++) {
            const int r = it*8 + warp;
            __half* base = Qs + r*FQH + DNOPE;
            float xe = __half2float(base[2*lane]);
            float xo = __half2float(base[2*lane + 1]);
            float ph = (float)(qt*BR + r) * inv;
            float sn, cs;
            sincosf(ph, &sn, &cs);
            __syncwarp();
            base[lane]      = __float2half_rn(xe*cs - xo*sn);
            base[lane + 32] = __float2half_rn(xo*cs + xe*sn);
            __syncwarp();
        }
    }

    float m0 = -INFINITY, m1 = -INFINITY, l0 = 0.f, l1 = 0.f;
    float o[16][4];
#pragma unroll
    for (int nt = 0; nt < 16; nt++)
#pragma unroll
        for (int r = 0; r < 4; r++) o[nt][r] = 0.f;

    for (int j = 0; j <= jmax; j++) {
        __syncthreads();
        if (j + 1 <= jmax) issue_tile(j + 1, (j + 1) & 1);
        CP_COMMIT();
        CP_WAIT1();
        __syncthreads();

        const int off = j*BC - qt*BR;
        if (off > wr0 + 15) continue;
        const bool needMask = (off + BC - 1 > wr0);

        const __half* Ksb = Ks + (j & 1)*BC*FQH;
        const __half* Vtb = Vt + (j & 1)*DV*FVH;

        float accS[4][4];
#pragma unroll
        for (int nt = 0; nt < 4; nt++)
#pragma unroll
            for (int r = 0; r < 4; r++) accS[nt][r] = 0.f;

#pragma unroll
        for (int k = 0; k < 12; k++) {
            const int k0 = k * 16;
            uint32_t a0 = *(const uint32_t*)(Qs + (wr0 + gr)*FQH     + k0 + 2*tc);
            uint32_t a1 = *(const uint32_t*)(Qs + (wr0 + gr + 8)*FQH + k0 + 2*tc);
            uint32_t a2 = *(const uint32_t*)(Qs + (wr0 + gr)*FQH     + k0 + 8 + 2*tc);
            uint32_t a3 = *(const uint32_t*)(Qs + (wr0 + gr + 8)*FQH + k0 + 8 + 2*tc);
#pragma unroll
            for (int nt = 0; nt < 4; nt++) {
                uint32_t b0 = *(const uint32_t*)(Ksb + (nt*8 + gr)*FQH + k0 + 2*tc);
                uint32_t b1 = *(const uint32_t*)(Ksb + (nt*8 + gr)*FQH + k0 + 8 + 2*tc);
                MMA_F16(accS[nt], a0, a1, a2, a3, b0, b1);
            }
        }

        if (needMask) {
            const int r0 = wr0 + gr, r1 = r0 + 8;
#pragma unroll
            for (int nt = 0; nt < 4; nt++) {
                const int c0 = nt*8 + 2*tc + off;
                accS[nt][0] = (c0     <= r0) ? accS[nt][0]*scale : -INFINITY;
                accS[nt][1] = (c0 + 1 <= r0) ? accS[nt][1]*scale : -INFINITY;
                accS[nt][2] = (c0     <= r1) ? accS[nt][2]*scale : -INFINITY;
                accS[nt][3] = (c0 + 1 <= r1) ? accS[nt][3]*scale : -INFINITY;
            }
        } else {
#pragma unroll
            for (int nt = 0; nt < 4; nt++)
#pragma unroll
                for (int r = 0; r < 4; r++) accS[nt][r] *= scale;
        }

        float rm0 = -INFINITY, rm1 = -INFINITY;
#pragma unroll
        for (int nt = 0; nt < 4; nt++) {
            rm0 = fmaxf(rm0, fmaxf(accS[nt][0], accS[nt][1]));
            rm1 = fmaxf(rm1, fmaxf(accS[nt][2], accS[nt][3]));
        }
        rm0 = fmaxf(rm0, __shfl_xor_sync(0xffffffffu, rm0, 1));
        rm0 = fmaxf(rm0, __shfl_xor_sync(0xffffffffu, rm0, 2));
        rm1 = fmaxf(rm1, __shfl_xor_sync(0xffffffffu, rm1, 1));
        rm1 = fmaxf(rm1, __shfl_xor_sync(0xffffffffu, rm1, 2));

        const float mn0 = fmaxf(m0, rm0), mn1 = fmaxf(m1, rm1);
        const float al0 = __expf(m0 - mn0), al1 = __expf(m1 - mn1);
        m0 = mn0; m1 = mn1;

        float rs0 = 0.f, rs1 = 0.f;
#pragma unroll
        for (int nt = 0; nt < 4; nt++) {
            float p0 = __expf(accS[nt][0] - mn0);
            float p1 = __expf(accS[nt][1] - mn0);
            float p2 = __expf(accS[nt][2] - mn1);
            float p3 = __expf(accS[nt][3] - mn1);
            rs0 += p0 + p1; rs1 += p2 + p3;
            const int c0 = nt*8 + 2*tc;
            *(__half2*)&Ps[(wr0 + gr)*FPH + c0]     = __floats2half2_rn(p0, p1);
            *(__half2*)&Ps[(wr0 + gr + 8)*FPH + c0] = __floats2half2_rn(p2, p3);
        }
        rs0 += __shfl_xor_sync(0xffffffffu, rs0, 1);
        rs0 += __shfl_xor_sync(0xffffffffu, rs0, 2);
        rs1 += __shfl_xor_sync(0xffffffffu, rs1, 1);
        rs1 += __shfl_xor_sync(0xffffffffu, rs1, 2);
        l0 = l0*al0 + rs0;
        l1 = l1*al1 + rs1;

#pragma unroll
        for (int nt = 0; nt < 16; nt++) {
            o[nt][0] *= al0; o[nt][1] *= al0;
            o[nt][2] *= al1; o[nt][3] *= al1;
        }
        __syncwarp();

#pragma unroll
        for (int k = 0; k < 2; k++) {
            const int k0 = k * 16;
            uint32_t a0 = *(const uint32_t*)(Ps + (wr0 + gr)*FPH     + k0 + 2*tc);
            uint32_t a1 = *(const uint32_t*)(Ps + (wr0 + gr + 8)*FPH + k0 + 2*tc);
            uint32_t a2 = *(const uint32_t*)(Ps + (wr0 + gr)*FPH     + k0 + 8 + 2*tc);
            uint32_t a3 = *(const uint32_t*)(Ps + (wr0 + gr + 8)*FPH + k0 + 8 + 2*tc);
#pragma unroll
            for (int nt = 0; nt < 16; nt++) {
                uint32_t b0 = *(const uint32_t*)(Vtb + (nt*8 + gr)*FVH + k0 + 2*tc);
                uint32_t b1 = *(const uint32_t*)(Vtb + (nt*8 + gr)*FVH + k0 + 8 + 2*tc);
                MMA_F16(o[nt], a0, a1, a2, a3, b0, b1);
            }
        }
    }

    const float il0 = 1.0f / l0, il1 = 1.0f / l1;
    const int row0 = qrow0 + wr0 + gr;
#pragma unroll
    for (int nt = 0; nt < 16; nt++) {
        const int col = h*DV + nt*8 + 2*tc;
        *(__half2*)&attn[(size_t)row0*ATTN_LD + col] =
            __floats2half2_rn(o[nt][0]*il0, o[nt][1]*il0);
        *(__half2*)&attn[(size_t)(row0 + 8)*ATTN_LD + col] =
            __floats2half2_rn(o[nt][2]*il1, o[nt][3]*il1);
    }
}

// ---------------- launch ----------------
extern "C" void kernel_launch(void* const* d_in, const int* in_sizes, int n_in,
                              void* d_out, int out_size)
{
    const float* hid    = (const float*)d_in[0];
    const float* w_dq   = (const float*)d_in[1];
    const float* q_ln   = (const float*)d_in[2];
    const float* w_uq   = (const float*)d_in[3];
    const float* kv_a_w = (const float*)d_in[4];
    const float* kv_ln  = (const float*)d_in[5];
    const float* kv_b_w = (const float*)d_in[6];
    const float* o_w    = (const float*)d_in[7];
    float* out = (float*)d_out;

    __half *hidh, *qaraw, *ckvall, *qah, *ckvh, *qh, *kvh, *vTh, *kpeh, *attnh;
    __half *wAT, *wuqT, *kvbT, *owT;
    cudaGetSymbolAddress((void**)&hidh,  g_hidh);
    cudaGetSymbolAddress((void**)&qaraw, g_qaraw);
    cudaGetSymbolAddress((void**)&ckvall,g_ckvall);
    cudaGetSymbolAddress((void**)&qah,   g_qah);
    cudaGetSymbolAddress((void**)&ckvh,  g_ckvh);
    cudaGetSymbolAddress((void**)&qh,    g_qh);
    cudaGetSymbolAddress((void**)&kvh,   g_kvh);
    cudaGetSymbolAddress((void**)&vTh,   g_vTh);
    cudaGetSymbolAddress((void**)&kpeh,  g_kpeh);
    cudaGetSymbolAddress((void**)&attnh, g_attnh);
    cudaGetSymbolAddress((void**)&wAT,   g_wAT);
    cudaGetSymbolAddress((void**)&wuqT,  g_wuqT);
    cudaGetSymbolAddress((void**)&kvbT,  g_kvbT);
    cudaGetSymbolAddress((void**)&owT,   g_owT);

    cudaFuncSetAttribute(flash_h_kernel, cudaFuncAttributeMaxDynamicSharedMemorySize, FLASH_SMEM);
    cudaFuncSetAttribute(h16_gemm<float>, cudaFuncAttributeMaxDynamicSharedMemorySize, H_SMEM);
    cudaFuncSetAttribute(h16_gemm<__half>, cudaFuncAttributeMaxDynamicSharedMemorySize, H_SMEM);

    // pre-pass: hidden -> half; all weight transposes fused in one launch
    f2h_kernel<<<(NROWS*HIDDEN/4 + 255)/256, 256>>>(hid, hidh, NROWS*HIDDEN/4);
    {
        TJob j0 = { w_dq,   wAT,                          HIDDEN, QLORA,  0 };
        int t0 = (HIDDEN/64)*(QLORA/32);
        TJob j1 = { kv_a_w, wAT + (size_t)QLORA*HIDDEN,   HIDDEN, CKV_LD, t0 };
        int t1 = t0 + (HIDDEN/64)*(CKV_LD/32);
        TJob j2 = { w_uq,   wuqT,                         QLORA,  Q_LD,   t1 };
        int t2 = t1 + (QLORA/64)*(Q_LD/32);
        TJob j3 = { kv_b_w, kvbT,                         KVLORA, KV_LD,  t2 };
        int t3 = t2 + (KVLORA/64)*(KV_LD/32);
        TJob j4 = { o_w,    owT,                          ATTN_LD, HIDDEN, t3 };
        int t4 = t3 + (ATTN_LD/64)*(HIDDEN/32);
        transpose5_kernel<<<t4, 256>>>(j0, j1, j2, j3, j4);
    }

    // fused [q_a | ckv_pe] = hidden @ [w_dq | kv_a_w]  [4096, 2112] k=2048 (half, split)
    h16_gemm<__half><<<dim3((NFUSE+127)/128, NROWS/128), 256, H_SMEM>>>(
        hidh, wAT, qaraw, NROWS, NFUSE, HIDDEN, QLORA, ckvall, CKV_LD, QLORA);
    // fused RMSNorm(qa) + RMSNorm(ckv) + RoPE(k_pe)
    normfuse_kernel<<<NROWS, 256>>>(qaraw, ckvall, q_ln, kv_ln, qah, ckvh, kpeh);
    // q = q_a_ln @ w_uq          [4096,3072] k=1536 (half out, NO rope here)
    h16_gemm<__half><<<dim3(Q_LD/128, NROWS/128), 256, H_SMEM>>>(
        qah, wuqT, qh, NROWS, Q_LD, QLORA, Q_LD, (__half*)nullptr, 0, 1<<30);
    // kv = ckv_ln @ kv_b_w       [4096,4096] k=512 (half out)
    h16_gemm<__half><<<dim3(KV_LD/128, NROWS/128), 256, H_SMEM>>>(
        ckvh, kvbT, kvh, NROWS, KV_LD, KVLORA, KV_LD, (__half*)nullptr, 0, 1<<30);
    // V transpose: kvh -> vT[h][dv][row]
    vtrans_kernel<<<dim3(NROWS/32, NH*4), dim3(32,8)>>>(kvh, vTh);
    // all-fp16 causal flash attention (q-RoPE applied in-kernel) -> attnh
    flash_h_kernel<<<dim3(S_LEN/BR, BATCH*NH), 256, FLASH_SMEM>>>(qh, kvh, vTh, kpeh, attnh);
    // out = attn @ o_w  [4096,2048] k=2048 (fp32 out)
    h16_gemm<float><<<dim3(HIDDEN/128, NROWS/128), 256, H_SMEM>>>(
        attnh, owT, out, NROWS, HIDDEN, ATTN_LD, HIDDEN, (float*)nullptr, 0, 1<<30);
}

// round 14
// speedup vs baseline: 1.0600x; 1.0180x over previous
#include <cuda_runtime.h>
#include <cuda_fp16.h>
#include <math.h>
#include <stdint.h>

// ---------------- problem constants ----------------
#define S_LEN   2048
#define BATCH   2
#define HIDDEN  2048
#define NH      16
#define QLORA   1536
#define KVLORA  512
#define DNOPE   128
#define DROPE   64
#define DV      128
#define DQ      192           // DNOPE + DROPE
#define NROWS   (BATCH*S_LEN) // 4096
#define CKV_LD  (KVLORA + DROPE) // 576
#define KV_LD   (NH*(DNOPE+DV))  // 4096
#define Q_LD    (NH*DQ)          // 3072
#define ATTN_LD (NH*DV)          // 2048
#define NFUSE   (QLORA + CKV_LD) // 2112

// ---------------- scratch (device globals; no runtime alloc) ----------------
__device__ __half g_hidh  [(size_t)NROWS*HIDDEN];
__device__ __half g_qaraw [(size_t)NROWS*QLORA];
__device__ __half g_ckvall[(size_t)NROWS*CKV_LD];
__device__ __half g_qah   [(size_t)NROWS*QLORA];
__device__ __half g_ckvh  [(size_t)NROWS*KVLORA];
__device__ __half g_qh    [(size_t)NROWS*Q_LD];     // q (half, UN-roped; rope in flash)
__device__ __half g_kvh   [(size_t)NROWS*KV_LD];    // only nope halves written/read
__device__ __half g_vTh   [(size_t)NH*DV*NROWS];    // V transposed [h][dv][row]
__device__ __half g_kpeh  [(size_t)NROWS*DROPE];
__device__ __half g_attnh [(size_t)NROWS*ATTN_LD];
__device__ __half g_wAT   [(size_t)NFUSE*HIDDEN];
__device__ __half g_wuqT  [(size_t)Q_LD*QLORA];
__device__ __half g_kvbT  [(size_t)KV_LD*KVLORA];
__device__ __half g_owT   [(size_t)HIDDEN*ATTN_LD];

// ---------------- helpers ----------------
#define MMA_F16(acc, a0,a1,a2,a3, b0,b1)                                        \
    asm volatile(                                                               \
        "mma.sync.aligned.m16n8k16.row.col.f32.f16.f16.f32 "                    \
        "{%0,%1,%2,%3}, {%4,%5,%6,%7}, {%8,%9}, {%0,%1,%2,%3};"                 \
        : "+f"(acc[0]), "+f"(acc[1]), "+f"(acc[2]), "+f"(acc[3])                \
        : "r"(a0), "r"(a1), "r"(a2), "r"(a3), "r"(b0), "r"(b1))

#define CP_ASYNC16(dst_u32, src_ptr)                                            \
    asm volatile("cp.async.cg.shared.global [%0], [%1], 16;"                    \
                 :: "r"(dst_u32), "l"(src_ptr))
#define CP_COMMIT() asm volatile("cp.async.commit_group;")
#define CP_WAIT1()  asm volatile("cp.async.wait_group 1;")

__device__ __forceinline__ uint32_t smem_u32(const void* p) {
    uint32_t a;
    asm("{ .reg .u64 t; cvta.to.shared.u64 t, %1; cvt.u32.u64 %0, t; }"
        : "=r"(a) : "l"(p));
    return a;
}

// ---------------- pre-pass kernels ----------------
__global__ void f2h_kernel(const float* __restrict__ src, __half* __restrict__ dst, int n4)
{
    int i = blockIdx.x * 256 + threadIdx.x;
    if (i < n4) {
        float4 v = ((const float4*)src)[i];
        ((__half2*)dst)[2*i]     = __floats2half2_rn(v.x, v.y);
        ((__half2*)dst)[2*i + 1] = __floats2half2_rn(v.z, v.w);
    }
}

// Fused transpose of all 5 weight matrices: src[R][C] fp32 -> dst[C][R] half.
struct TJob { const float* src; __half* dst; int R, C, tile0; };

__global__ __launch_bounds__(256) void transpose5_kernel(TJob j0, TJob j1, TJob j2, TJob j3, TJob j4)
{
    __shared__ float t[32][66];
    const int bid = blockIdx.x;
    TJob j;
    if      (bid < j1.tile0) j = j0;
    else if (bid < j2.tile0) j = j1;
    else if (bid < j3.tile0) j = j2;
    else if (bid < j4.tile0) j = j3;
    else                     j = j4;
    const int t_local = bid - j.tile0;
    const int rtiles  = j.R >> 6;
    const int tr = t_local % rtiles;
    const int tcb = t_local / rtiles;
    const int rbase = tr * 64, cbase = tcb * 32;
    const int tx = threadIdx.x & 31, ty = threadIdx.x >> 5;

#pragma unroll
    for (int it = 0; it < 8; it++) {
        int r = ty + it*8;
        t[tx][r] = j.src[(size_t)(rbase + r)*j.C + cbase + tx];
    }
    __syncthreads();
#pragma unroll
    for (int jj = 0; jj < 4; jj++) {
        int c = ty + jj*8;
        float2 v = *(float2*)&t[c][2*tx];
        *(__half2*)&j.dst[(size_t)(cbase + c)*j.R + rbase + 2*tx] =
            __floats2half2_rn(v.x, v.y);
    }
}

// ---------------- fp16 GEMM common ----------------
#define HS 3
#define HBK 64
#define HSTR 72
#define H_TILE_BYTES (128*HSTR*2)
#define H_SMEM (2*HS*H_TILE_BYTES)

// ---------------- single-job fp16 GEMM (templated output, split epilogue) ----------------
template <typename TOut>
__global__ __launch_bounds__(256, 2) void h16_gemm(
    const __half* __restrict__ A, const __half* __restrict__ Bt,
    TOut* __restrict__ C, int M, int N, int K, int ldc,
    TOut* __restrict__ C2, int ldc2, int nsplit)
{
    extern __shared__ char hsm[];
    const uint32_t smb = smem_u32(hsm);
    const __half* As_h = (const __half*)hsm;
    const __half* Bs_h = (const __half*)(hsm + HS*H_TILE_BYTES);

    const int tid  = threadIdx.x;
    const int lane = tid & 31;
    const int warp = tid >> 5;
    const int wm0  = (warp >> 2) * 64;
    const int wn0  = (warp & 3) * 32;
    const int gr   = lane >> 2;
    const int tc   = lane & 3;

    const int bm = blockIdx.y * 128;
    const int bn = blockIdx.x * 128;

    float acc[4][4][4];
#pragma unroll
    for (int mt = 0; mt < 4; mt++)
#pragma unroll
        for (int nt = 0; nt < 4; nt++)
#pragma unroll
            for (int r = 0; r < 4; r++) acc[mt][nt][r] = 0.0f;

    const int r0 = tid >> 3;
    const int ch = tid & 7;
    const __half* Asrc[4]; const __half* Bsrc[4];
    uint32_t soff[4];
#pragma unroll
    for (int i = 0; i < 4; i++) {
        const int rr = r0 + 32*i;
        Asrc[i] = A + (size_t)(bm + rr)*K + ch*8;
        int nr = bn + rr; if (nr > N-1) nr = N-1;
        Bsrc[i] = Bt + (size_t)nr*K + ch*8;
        soff[i] = (uint32_t)(rr*144 + ch*16);
    }
    const uint32_t a_base = smb;
    const uint32_t b_base = smb + HS*H_TILE_BYTES;

    const int ntiles = K >> 6;

    auto issue_stage = [&](int t) {
        const int kg = t * HBK;
        const uint32_t as = a_base + (t % HS) * H_TILE_BYTES;
        const uint32_t bs = b_base + (t % HS) * H_TILE_BYTES;
#pragma unroll
        for (int i = 0; i < 4; i++) CP_ASYNC16(as + soff[i], Asrc[i] + kg);
#pragma unroll
        for (int i = 0; i < 4; i++) CP_ASYNC16(bs + soff[i], Bsrc[i] + kg);
    };

    issue_stage(0); CP_COMMIT();
    issue_stage(1); CP_COMMIT();

    for (int kt = 0; kt < ntiles; kt++) {
        CP_WAIT1();
        __syncthreads();
        if (kt + 2 < ntiles) issue_stage(kt + 2);
        CP_COMMIT();

        const __half* At  = As_h + (kt % HS) * (128*HSTR);
        const __half* Bts = Bs_h + (kt % HS) * (128*HSTR);
#pragma unroll
        for (int ks = 0; ks < 4; ks++) {
            const int k0 = ks * 16;
            uint32_t af[4][4], bf[4][2];
#pragma unroll
            for (int mt = 0; mt < 4; mt++) {
                const int row = wm0 + mt*16 + gr;
                af[mt][0] = *(const uint32_t*)(At + row*HSTR     + k0 + 2*tc);
                af[mt][1] = *(const uint32_t*)(At + (row+8)*HSTR + k0 + 2*tc);
                af[mt][2] = *(const uint32_t*)(At + row*HSTR     + k0 + 8 + 2*tc);
                af[mt][3] = *(const uint32_t*)(At + (row+8)*HSTR + k0 + 8 + 2*tc);
            }
#pragma unroll
            for (int nt = 0; nt < 4; nt++) {
                const int cr = wn0 + nt*8 + gr;
                bf[nt][0] = *(const uint32_t*)(Bts + cr*HSTR + k0 + 2*tc);
                bf[nt][1] = *(const uint32_t*)(Bts + cr*HSTR + k0 + 8 + 2*tc);
            }
#pragma unroll
            for (int mt = 0; mt < 4; mt++)
#pragma unroll
                for (int nt = 0; nt < 4; nt++)
                    MMA_F16(acc[mt][nt], af[mt][0], af[mt][1], af[mt][2], af[mt][3],
                            bf[nt][0], bf[nt][1]);
        }
    }

#pragma unroll
    for (int mt = 0; mt < 4; mt++) {
        const int row0 = bm + wm0 + mt * 16 + gr;
#pragma unroll
        for (int nt = 0; nt < 4; nt++) {
            const int col = bn + wn0 + nt * 8 + tc * 2;
            if (col >= N) continue;
            TOut* dst;
            size_t idx;
            int ld;
            if (col < nsplit) { dst = C;  ld = ldc;  idx = (size_t)row0*ldc  + col; }
            else              { dst = C2; ld = ldc2; idx = (size_t)row0*ldc2 + (col - nsplit); }
            const size_t idx2 = idx + (size_t)8 * ld;
            if constexpr (sizeof(TOut) == 4) {
                *(float2*)&((float*)dst)[idx]  = make_float2(acc[mt][nt][0], acc[mt][nt][1]);
                *(float2*)&((float*)dst)[idx2] = make_float2(acc[mt][nt][2], acc[mt][nt][3]);
            } else {
                *(__half2*)&((__half*)dst)[idx]  = __floats2half2_rn(acc[mt][nt][0], acc[mt][nt][1]);
                *(__half2*)&((__half*)dst)[idx2] = __floats2half2_rn(acc[mt][nt][2], acc[mt][nt][3]);
            }
        }
    }
}

// ---------------- kv GEMM with fused V-transpose epilogue ----------------
// N = KV_LD = 4096. Even col-tiles (bn%256==0) are K-nope -> write kvh rows.
// Odd col-tiles (bn%256==128) are V -> write ONLY vT[h*128+dv][rows] via smem transpose.
__global__ __launch_bounds__(256, 2) void kv_gemm_vt(
    const __half* __restrict__ A, const __half* __restrict__ Bt,
    __half* __restrict__ kvh, __half* __restrict__ vT, int K)
{
    extern __shared__ char hsm[];
    const uint32_t smb = smem_u32(hsm);
    const __half* As_h = (const __half*)hsm;
    const __half* Bs_h = (const __half*)(hsm + HS*H_TILE_BYTES);

    const int tid  = threadIdx.x;
    const int lane = tid & 31;
    const int warp = tid >> 5;
    const int wm0  = (warp >> 2) * 64;
    const int wn0  = (warp & 3) * 32;
    const int gr   = lane >> 2;
    const int tc   = lane & 3;

    const int bm = blockIdx.y * 128;
    const int bn = blockIdx.x * 128;

    float acc[4][4][4];
#pragma unroll
    for (int mt = 0; mt < 4; mt++)
#pragma unroll
        for (int nt = 0; nt < 4; nt++)
#pragma unroll
            for (int r = 0; r < 4; r++) acc[mt][nt][r] = 0.0f;

    const int r0 = tid >> 3;
    const int ch = tid & 7;
    const __half* Asrc[4]; const __half* Bsrc[4];
    uint32_t soff[4];
#pragma unroll
    for (int i = 0; i < 4; i++) {
        const int rr = r0 + 32*i;
        Asrc[i] = A + (size_t)(bm + rr)*K + ch*8;
        Bsrc[i] = Bt + (size_t)(bn + rr)*K + ch*8;
        soff[i] = (uint32_t)(rr*144 + ch*16);
    }
    const uint32_t a_base = smb;
    const uint32_t b_base = smb + HS*H_TILE_BYTES;

    const int ntiles = K >> 6;     // 8 for K=512

    auto issue_stage = [&](int t) {
        const int kg = t * HBK;
        const uint32_t as = a_base + (t % HS) * H_TILE_BYTES;
        const uint32_t bs = b_base + (t % HS) * H_TILE_BYTES;
#pragma unroll
        for (int i = 0; i < 4; i++) CP_ASYNC16(as + soff[i], Asrc[i] + kg);
#pragma unroll
        for (int i = 0; i < 4; i++) CP_ASYNC16(bs + soff[i], Bsrc[i] + kg);
    };

    issue_stage(0); CP_COMMIT();
    issue_stage(1); CP_COMMIT();

    for (int kt = 0; kt < ntiles; kt++) {
        CP_WAIT1();
        __syncthreads();
        if (kt + 2 < ntiles) issue_stage(kt + 2);
        CP_COMMIT();

        const __half* At  = As_h + (kt % HS) * (128*HSTR);
        const __half* Bts = Bs_h + (kt % HS) * (128*HSTR);
#pragma unroll
        for (int ks = 0; ks < 4; ks++) {
            const int k0 = ks * 16;
            uint32_t af[4][4], bf[4][2];
#pragma unroll
            for (int mt = 0; mt < 4; mt++) {
                const int row = wm0 + mt*16 + gr;
                af[mt][0] = *(const uint32_t*)(At + row*HSTR     + k0 + 2*tc);
                af[mt][1] = *(const uint32_t*)(At + (row+8)*HSTR + k0 + 2*tc);
                af[mt][2] = *(const uint32_t*)(At + row*HSTR     + k0 + 8 + 2*tc);
                af[mt][3] = *(const uint32_t*)(At + (row+8)*HSTR + k0 + 8 + 2*tc);
            }
#pragma unroll
            for (int nt = 0; nt < 4; nt++) {
                const int cr = wn0 + nt*8 + gr;
                bf[nt][0] = *(const uint32_t*)(Bts + cr*HSTR + k0 + 2*tc);
                bf[nt][1] = *(const uint32_t*)(Bts + cr*HSTR + k0 + 8 + 2*tc);
            }
#pragma unroll
            for (int mt = 0; mt < 4; mt++)
#pragma unroll
                for (int nt = 0; nt < 4; nt++)
                    MMA_F16(acc[mt][nt], af[mt][0], af[mt][1], af[mt][2], af[mt][3],
                            bf[nt][0], bf[nt][1]);
        }
    }

    if ((bn & 255) == 0) {
        // K-nope tile: normal row-major write to kvh
#pragma unroll
        for (int mt = 0; mt < 4; mt++) {
            const int row0 = bm + wm0 + mt * 16 + gr;
#pragma unroll
            for (int nt = 0; nt < 4; nt++) {
                const int col = bn + wn0 + nt * 8 + tc * 2;
                *(__half2*)&kvh[(size_t)row0*KV_LD + col] =
                    __floats2half2_rn(acc[mt][nt][0], acc[mt][nt][1]);
                *(__half2*)&kvh[(size_t)(row0 + 8)*KV_LD + col] =
                    __floats2half2_rn(acc[mt][nt][2], acc[mt][nt][3]);
            }
        }
    } else {
        // V tile: transpose through smem, write vT[h*DV+dv][rows] only
        __syncthreads();                 // all warps done with stage buffers
        __half* st = (__half*)hsm;       // 128 x 136 halves = 34.8 KB
#pragma unroll
        for (int mt = 0; mt < 4; mt++) {
            const int rowl = wm0 + mt * 16 + gr;
#pragma unroll
            for (int nt = 0; nt < 4; nt++) {
                const int coll = wn0 + nt * 8 + tc * 2;
                st[(coll)    *136 + rowl]     = __float2half_rn(acc[mt][nt][0]);
                st[(coll + 1)*136 + rowl]     = __float2half_rn(acc[mt][nt][1]);
                st[(coll)    *136 + rowl + 8] = __float2half_rn(acc[mt][nt][2]);
                st[(coll + 1)*136 + rowl + 8] = __float2half_rn(acc[mt][nt][3]);
            }
        }
        __syncthreads();
        const int hh = bn >> 8;          // head
        __half* vbase = vT + (size_t)hh * DV * NROWS;
#pragma unroll
        for (int i = 0; i < 8; i++) {
            int idx = tid + i * 256;
            int dv = idx >> 4, c8 = (idx & 15) * 8;
            *(uint4*)&vbase[(size_t)dv * NROWS + bm + c8] = *(uint4*)&st[dv*136 + c8];
        }
    }
}

// ---------------- fused RMSNorm(qa) + RMSNorm(ckv) + RoPE(k_pe) ----------------
__global__ void normfuse_kernel(const __half* __restrict__ qaraw,
                                const __half* __restrict__ ckvall,
                                const float* __restrict__ q_ln,
                                const float* __restrict__ kv_ln,
                                __half* __restrict__ qah,
                                __half* __restrict__ ckvh,
                                __half* __restrict__ kpeh)
{
    __shared__ float red1[256], red2[256];
    const int row = blockIdx.x;
    const int tid = threadIdx.x;
    const __half* p1 = qaraw + (size_t)row*QLORA;
    const __half* p2 = ckvall + (size_t)row*CKV_LD;

    float ss1 = 0.f;
    for (int c = tid; c < QLORA/2; c += 256) {
        float2 v = __half22float2(((const __half2*)p1)[c]);
        ss1 += v.x*v.x + v.y*v.y;
    }
    float ss2 = 0.f;
    {
        float2 v = __half22float2(((const __half2*)p2)[tid]);
        ss2 = v.x*v.x + v.y*v.y;
    }
    red1[tid] = ss1; red2[tid] = ss2;
    __syncthreads();
    for (int s = 128; s; s >>= 1) {
        if (tid < s) { red1[tid] += red1[tid + s]; red2[tid] += red2[tid + s]; }
        __syncthreads();
    }
    const float sc1 = rsqrtf(red1[0] / (float)QLORA  + 1e-6f);
    const float sc2 = rsqrtf(red2[0] / (float)KVLORA + 1e-6f);

    __half* d1 = qah  + (size_t)row*QLORA;
    __half* d2 = ckvh + (size_t)row*KVLORA;
    for (int c = tid; c < QLORA; c += 256)
        d1[c] = __float2half_rn(__half2float(p1[c]) * sc1 * q_ln[c]);
    for (int c = tid; c < KVLORA; c += 256)
        d2[c] = __float2half_rn(__half2float(p2[c]) * sc2 * kv_ln[c]);

    if (tid < 32) {
        const int lane = tid;
        const __half* base = p2 + KVLORA;
        float xe = __half2float(base[2*lane]), xo = __half2float(base[2*lane + 1]);
        float inv = 1.0f / powf(10000.0f, (2.0f * (float)lane) / 64.0f);
        float ph = (float)(row % S_LEN) * inv;
        float sn, cs;
        sincosf(ph, &sn, &cs);
        kpeh[(size_t)row*DROPE + lane]      = __float2half_rn(xe*cs - xo*sn);
        kpeh[(size_t)row*DROPE + lane + 32] = __float2half_rn(xo*cs + xe*sn);
    }
}

// ---------------- all-fp16 tensor-core causal flash attention (q-RoPE fused) ----------------
#define FQH 200
#define FVH 40
#define FPH 40
#define BR 128
#define BC 32
#define FLASH_SMEM ((BR*FQH + 2*BC*FQH + 2*DV*FVH + BR*FPH)*2)

__global__ __launch_bounds__(256, 2) void flash_h_kernel(
    const __half* __restrict__ q, const __half* __restrict__ kvh,
    const __half* __restrict__ vT, const __half* __restrict__ kpeh,
    __half* __restrict__ attn)
{
    extern __shared__ __half smh[];
    __half* Qs = smh;
    __half* Ks = Qs + BR*FQH;
    __half* Vt = Ks + 2*BC*FQH;
    __half* Ps = Vt + 2*DV*FVH;

    const int tid  = threadIdx.x;
    const int lane = tid & 31;
    const int warp = tid >> 5;
    const int gr   = lane >> 2;
    const int tc   = lane & 3;
    const int qt = (gridDim.x - 1) - blockIdx.x;
    const int b  = blockIdx.y >> 4;
    const int h  = blockIdx.y & 15;
    const float scale = 0.07216878364870323f; // 1/sqrt(192)

    const int qrow0 = b*S_LEN + qt*BR;
    const int wr0   = warp * 16;

    uint32_t ksm[2], vsm[2];
    ksm[0] = smem_u32(Ks);
    ksm[1] = smem_u32(Ks + BC*FQH);
    vsm[0] = smem_u32(Vt);
    vsm[1] = smem_u32(Vt + DV*FVH);

    const int jmax = 4*qt + 3;

    auto issue_tile = [&](int j, int buf) {
        const int krow0 = b*S_LEN + j*BC;
#pragma unroll
        for (int t = 0; t < 3; t++) {
            int idx = tid + t*256;
            int r = idx / 24, col8 = (idx % 24) * 8;
            const __half* src = (col8 < DNOPE)
                ? kvh + (size_t)(krow0 + r)*KV_LD + h*256 + col8
                : kpeh + (size_t)(krow0 + r)*DROPE + (col8 - DNOPE);
            CP_ASYNC16(ksm[buf] + (uint32_t)(r*FQH + col8)*2, src);
        }
#pragma unroll
        for (int t = 0; t < 2; t++) {
            int idx = tid + t*256;
            int r = idx >> 2, c8 = (idx & 3) * 8;
            const __half* src = vT + (size_t)(h*DV + r)*NROWS + krow0 + c8;
            CP_ASYNC16(vsm[buf] + (uint32_t)(r*FVH + c8)*2, src);
        }
    };

    issue_tile(0, 0);
    CP_COMMIT();

#pragma unroll
    for (int t = 0; t < 12; t++) {
        int idx = tid + t*256;
        int r = idx / 24, c = idx % 24;
        *(uint4*)&Qs[r*FQH + c*8] =
            *(const uint4*)(q + (size_t)(qrow0 + r)*Q_LD + h*DQ + c*8);
    }
    __syncthreads();

    // q-RoPE in smem
    {
        const float inv = 1.0f / powf(10000.0f, (2.0f * (float)lane) / 64.0f);
#pragma unroll
        for (int it = 0; it < 16; it++) {
            const int r = it*8 + warp;
            __half* base = Qs + r*FQH + DNOPE;
            float xe = __half2float(base[2*lane]);
            float xo = __half2float(base[2*lane + 1]);
            float ph = (float)(qt*BR + r) * inv;
            float sn, cs;
            sincosf(ph, &sn, &cs);
            __syncwarp();
            base[lane]      = __float2half_rn(xe*cs - xo*sn);
            base[lane + 32] = __float2half_rn(xo*cs + xe*sn);
            __syncwarp();
        }
    }

    float m0 = -INFINITY, m1 = -INFINITY, l0 = 0.f, l1 = 0.f;
    float o[16][4];
#pragma unroll
    for (int nt = 0; nt < 16; nt++)
#pragma unroll
        for (int r = 0; r < 4; r++) o[nt][r] = 0.f;

    for (int j = 0; j <= jmax; j++) {
        __syncthreads();
        if (j + 1 <= jmax) issue_tile(j + 1, (j + 1) & 1);
        CP_COMMIT();
        CP_WAIT1();
        __syncthreads();

        const int off = j*BC - qt*BR;
        if (off > wr0 + 15) continue;
        const bool needMask = (off + BC - 1 > wr0);

        const __half* Ksb = Ks + (j & 1)*BC*FQH;
        const __half* Vtb = Vt + (j & 1)*DV*FVH;

        float accS[4][4];
#pragma unroll
        for (int nt = 0; nt < 4; nt++)
#pragma unroll
            for (int r = 0; r < 4; r++) accS[nt][r] = 0.f;

#pragma unroll
        for (int k = 0; k < 12; k++) {
            const int k0 = k * 16;
            uint32_t a0 = *(const uint32_t*)(Qs + (wr0 + gr)*FQH     + k0 + 2*tc);
            uint32_t a1 = *(const uint32_t*)(Qs + (wr0 + gr + 8)*FQH + k0 + 2*tc);
            uint32_t a2 = *(const uint32_t*)(Qs + (wr0 + gr)*FQH     + k0 + 8 + 2*tc);
            uint32_t a3 = *(const uint32_t*)(Qs + (wr0 + gr + 8)*FQH + k0 + 8 + 2*tc);
#pragma unroll
            for (int nt = 0; nt < 4; nt++) {
                uint32_t b0 = *(const uint32_t*)(Ksb + (nt*8 + gr)*FQH + k0 + 2*tc);
                uint32_t b1 = *(const uint32_t*)(Ksb + (nt*8 + gr)*FQH + k0 + 8 + 2*tc);
                MMA_F16(accS[nt], a0, a1, a2, a3, b0, b1);
            }
        }

        if (needMask) {
            const int r0 = wr0 + gr, r1 = r0 + 8;
#pragma unroll
            for (int nt = 0; nt < 4; nt++) {
                const int c0 = nt*8 + 2*tc + off;
                accS[nt][0] = (c0     <= r0) ? accS[nt][0]*scale : -INFINITY;
                accS[nt][1] = (c0 + 1 <= r0) ? accS[nt][1]*scale : -INFINITY;
                accS[nt][2] = (c0     <= r1) ? accS[nt][2]*scale : -INFINITY;
                accS[nt][3] = (c0 + 1 <= r1) ? accS[nt][3]*scale : -INFINITY;
            }
        } else {
#pragma unroll
            for (int nt = 0; nt < 4; nt++)
#pragma unroll
                for (int r = 0; r < 4; r++) accS[nt][r] *= scale;
        }

        float rm0 = -INFINITY, rm1 = -INFINITY;
#pragma unroll
        for (int nt = 0; nt < 4; nt++) {
            rm0 = fmaxf(rm0, fmaxf(accS[nt][0], accS[nt][1]));
            rm1 = fmaxf(rm1, fmaxf(accS[nt][2], accS[nt][3]));
        }
        rm0 = fmaxf(rm0, __shfl_xor_sync(0xffffffffu, rm0, 1));
        rm0 = fmaxf(rm0, __shfl_xor_sync(0xffffffffu, rm0, 2));
        rm1 = fmaxf(rm1, __shfl_xor_sync(0xffffffffu, rm1, 1));
        rm1 = fmaxf(rm1, __shfl_xor_sync(0xffffffffu, rm1, 2));

        const float mn0 = fmaxf(m0, rm0), mn1 = fmaxf(m1, rm1);
        const float al0 = __expf(m0 - mn0), al1 = __expf(m1 - mn1);
        m0 = mn0; m1 = mn1;

        float rs0 = 0.f, rs1 = 0.f;
#pragma unroll
        for (int nt = 0; nt < 4; nt++) {
            float p0 = __expf(accS[nt][0] - mn0);
            float p1 = __expf(accS[nt][1] - mn0);
            float p2 = __expf(accS[nt][2] - mn1);
            float p3 = __expf(accS[nt][3] - mn1);
            rs0 += p0 + p1; rs1 += p2 + p3;
            const int c0 = nt*8 + 2*tc;
            *(__half2*)&Ps[(wr0 + gr)*FPH + c0]     = __floats2half2_rn(p0, p1);
            *(__half2*)&Ps[(wr0 + gr + 8)*FPH + c0] = __floats2half2_rn(p2, p3);
        }
        rs0 += __shfl_xor_sync(0xffffffffu, rs0, 1);
        rs0 += __shfl_xor_sync(0xffffffffu, rs0, 2);
        rs1 += __shfl_xor_sync(0xffffffffu, rs1, 1);
        rs1 += __shfl_xor_sync(0xffffffffu, rs1, 2);
        l0 = l0*al0 + rs0;
        l1 = l1*al1 + rs1;

#pragma unroll
        for (int nt = 0; nt < 16; nt++) {
            o[nt][0] *= al0; o[nt][1] *= al0;
            o[nt][2] *= al1; o[nt][3] *= al1;
        }
        __syncwarp();

#pragma unroll
        for (int k = 0; k < 2; k++) {
            const int k0 = k * 16;
            uint32_t a0 = *(const uint32_t*)(Ps + (wr0 + gr)*FPH     + k0 + 2*tc);
            uint32_t a1 = *(const uint32_t*)(Ps + (wr0 + gr + 8)*FPH + k0 + 2*tc);
            uint32_t a2 = *(const uint32_t*)(Ps + (wr0 + gr)*FPH     + k0 + 8 + 2*tc);
            uint32_t a3 = *(const uint32_t*)(Ps + (wr0 + gr + 8)*FPH + k0 + 8 + 2*tc);
#pragma unroll
            for (int nt = 0; nt < 16; nt++) {
                uint32_t b0 = *(const uint32_t*)(Vtb + (nt*8 + gr)*FVH + k0 + 2*tc);
                uint32_t b1 = *(const uint32_t*)(Vtb + (nt*8 + gr)*FVH + k0 + 8 + 2*tc);
                MMA_F16(o[nt], a0, a1, a2, a3, b0, b1);
            }
        }
    }

    const float il0 = 1.0f / l0, il1 = 1.0f / l1;
    const int row0 = qrow0 + wr0 + gr;
#pragma unroll
    for (int nt = 0; nt < 16; nt++) {
        const int col = h*DV + nt*8 + 2*tc;
        *(__half2*)&attn[(size_t)row0*ATTN_LD + col] =
            __floats2half2_rn(o[nt][0]*il0, o[nt][1]*il0);
        *(__half2*)&attn[(size_t)(row0 + 8)*ATTN_LD + col] =
            __floats2half2_rn(o[nt][2]*il1, o[nt][3]*il1);
    }
}

// ---------------- launch ----------------
extern "C" void kernel_launch(void* const* d_in, const int* in_sizes, int n_in,
                              void* d_out, int out_size)
{
    const float* hid    = (const float*)d_in[0];
    const float* w_dq   = (const float*)d_in[1];
    const float* q_ln   = (const float*)d_in[2];
    const float* w_uq   = (const float*)d_in[3];
    const float* kv_a_w = (const float*)d_in[4];
    const float* kv_ln  = (const float*)d_in[5];
    const float* kv_b_w = (const float*)d_in[6];
    const float* o_w    = (const float*)d_in[7];
    float* out = (float*)d_out;

    __half *hidh, *qaraw, *ckvall, *qah, *ckvh, *qh, *kvh, *vTh, *kpeh, *attnh;
    __half *wAT, *wuqT, *kvbT, *owT;
    cudaGetSymbolAddress((void**)&hidh,  g_hidh);
    cudaGetSymbolAddress((void**)&qaraw, g_qaraw);
    cudaGetSymbolAddress((void**)&ckvall,g_ckvall);
    cudaGetSymbolAddress((void**)&qah,   g_qah);
    cudaGetSymbolAddress((void**)&ckvh,  g_ckvh);
    cudaGetSymbolAddress((void**)&qh,    g_qh);
    cudaGetSymbolAddress((void**)&kvh,   g_kvh);
    cudaGetSymbolAddress((void**)&vTh,   g_vTh);
    cudaGetSymbolAddress((void**)&kpeh,  g_kpeh);
    cudaGetSymbolAddress((void**)&attnh, g_attnh);
    cudaGetSymbolAddress((void**)&wAT,   g_wAT);
    cudaGetSymbolAddress((void**)&wuqT,  g_wuqT);
    cudaGetSymbolAddress((void**)&kvbT,  g_kvbT);
    cudaGetSymbolAddress((void**)&owT,   g_owT);

    cudaFuncSetAttribute(flash_h_kernel, cudaFuncAttributeMaxDynamicSharedMemorySize, FLASH_SMEM);
    cudaFuncSetAttribute(h16_gemm<float>, cudaFuncAttributeMaxDynamicSharedMemorySize, H_SMEM);
    cudaFuncSetAttribute(h16_gemm<__half>, cudaFuncAttributeMaxDynamicSharedMemorySize, H_SMEM);
    cudaFuncSetAttribute(kv_gemm_vt, cudaFuncAttributeMaxDynamicSharedMemorySize, H_SMEM);

    // pre-pass: hidden -> half; all weight transposes fused in one launch
    f2h_kernel<<<(NROWS*HIDDEN/4 + 255)/256, 256>>>(hid, hidh, NROWS*HIDDEN/4);
    {
        TJob j0 = { w_dq,   wAT,                          HIDDEN, QLORA,  0 };
        int t0 = (HIDDEN/64)*(QLORA/32);
        TJob j1 = { kv_a_w, wAT + (size_t)QLORA*HIDDEN,   HIDDEN, CKV_LD, t0 };
        int t1 = t0 + (HIDDEN/64)*(CKV_LD/32);
        TJob j2 = { w_uq,   wuqT,                         QLORA,  Q_LD,   t1 };
        int t2 = t1 + (QLORA/64)*(Q_LD/32);
        TJob j3 = { kv_b_w, kvbT,                         KVLORA, KV_LD,  t2 };
        int t3 = t2 + (KVLORA/64)*(KV_LD/32);
        TJob j4 = { o_w,    owT,                          ATTN_LD, HIDDEN, t3 };
        int t4 = t3 + (ATTN_LD/64)*(HIDDEN/32);
        transpose5_kernel<<<t4, 256>>>(j0, j1, j2, j3, j4);
    }

    // fused [q_a | ckv_pe] = hidden @ [w_dq | kv_a_w]  [4096, 2112] k=2048 (half, split)
    h16_gemm<__half><<<dim3((NFUSE+127)/128, NROWS/128), 256, H_SMEM>>>(
        hidh, wAT, qaraw, NROWS, NFUSE, HIDDEN, QLORA, ckvall, CKV_LD, QLORA);
    // fused RMSNorm(qa) + RMSNorm(ckv) + RoPE(k_pe)
    normfuse_kernel<<<NROWS, 256>>>(qaraw, ckvall, q_ln, kv_ln, qah, ckvh, kpeh);
    // q = q_a_ln @ w_uq          [4096,3072] k=1536 (half out, rope in flash)
    h16_gemm<__half><<<dim3(Q_LD/128, NROWS/128), 256, H_SMEM>>>(
        qah, wuqT, qh, NROWS, Q_LD, QLORA, Q_LD, (__half*)nullptr, 0, 1<<30);
    // kv = ckv_ln @ kv_b_w  [4096,4096] k=512: nope->kvh, V->vT (fused transpose)
    kv_gemm_vt<<<dim3(KV_LD/128, NROWS/128), 256, H_SMEM>>>(ckvh, kvbT, kvh, vTh, KVLORA);
    // all-fp16 causal flash attention (q-RoPE in-kernel) -> attnh
    flash_h_kernel<<<dim3(S_LEN/BR, BATCH*NH), 256, FLASH_SMEM>>>(qh, kvh, vTh, kpeh, attnh);
    // out = attn @ o_w  [4096,2048] k=2048 (fp32 out)
    h16_gemm<float><<<dim3(HIDDEN/128, NROWS/128), 256, H_SMEM>>>(
        attnh, owT, out, NROWS, HIDDEN, ATTN_LD, HIDDEN, (float*)nullptr, 0, 1<<30);
}

// round 15
// speedup vs baseline: 1.0636x; 1.0034x over previous
#include <cuda_runtime.h>
#include <cuda_fp16.h>
#include <math.h>
#include <stdint.h>

// ---------------- problem constants ----------------
#define S_LEN   2048
#define BATCH   2
#define HIDDEN  2048
#define NH      16
#define QLORA   1536
#define KVLORA  512
#define DNOPE   128
#define DROPE   64
#define DV      128
#define DQ      192           // DNOPE + DROPE
#define NROWS   (BATCH*S_LEN) // 4096
#define CKV_LD  (KVLORA + DROPE) // 576
#define KV_LD   (NH*(DNOPE+DV))  // 4096
#define Q_LD    (NH*DQ)          // 3072
#define ATTN_LD (NH*DV)          // 2048
#define NFUSE   (QLORA + CKV_LD) // 2112

// ---------------- scratch (device globals; no runtime alloc) ----------------
__device__ __half g_hidh  [(size_t)NROWS*HIDDEN];
__device__ __half g_qaraw [(size_t)NROWS*QLORA];
__device__ __half g_ckvall[(size_t)NROWS*CKV_LD];
__device__ __half g_qah   [(size_t)NROWS*QLORA];
__device__ __half g_ckvh  [(size_t)NROWS*KVLORA];
__device__ __half g_qh    [(size_t)NROWS*Q_LD];     // q (half, UN-roped; rope in flash)
__device__ __half g_kvh   [(size_t)NROWS*KV_LD];    // only nope halves written/read
__device__ __half g_vTh   [(size_t)NH*DV*NROWS];    // V transposed [h][dv][row]
__device__ __half g_kpeh  [(size_t)NROWS*DROPE];
__device__ __half g_attnh [(size_t)NROWS*ATTN_LD];
__device__ __half g_wAT   [(size_t)NFUSE*HIDDEN];
__device__ __half g_wuqT  [(size_t)Q_LD*QLORA];
__device__ __half g_kvbT  [(size_t)KV_LD*KVLORA];
__device__ __half g_owT   [(size_t)HIDDEN*ATTN_LD];

// ---------------- helpers ----------------
#define MMA_F16(acc, a0,a1,a2,a3, b0,b1)                                        \
    asm volatile(                                                               \
        "mma.sync.aligned.m16n8k16.row.col.f32.f16.f16.f32 "                    \
        "{%0,%1,%2,%3}, {%4,%5,%6,%7}, {%8,%9}, {%0,%1,%2,%3};"                 \
        : "+f"(acc[0]), "+f"(acc[1]), "+f"(acc[2]), "+f"(acc[3])                \
        : "r"(a0), "r"(a1), "r"(a2), "r"(a3), "r"(b0), "r"(b1))

#define CP_ASYNC16(dst_u32, src_ptr)                                            \
    asm volatile("cp.async.cg.shared.global [%0], [%1], 16;"                    \
                 :: "r"(dst_u32), "l"(src_ptr))
#define CP_COMMIT() asm volatile("cp.async.commit_group;")
#define CP_WAIT1()  asm volatile("cp.async.wait_group 1;")

__device__ __forceinline__ uint32_t smem_u32(const void* p) {
    uint32_t a;
    asm("{ .reg .u64 t; cvta.to.shared.u64 t, %1; cvt.u32.u64 %0, t; }"
        : "=r"(a) : "l"(p));
    return a;
}

// ---------------- pre-pass: 5 transposes + hidden f32->f16 copy, ONE launch ----------------
struct TJob { const float* src; __half* dst; int R, C, tile0; };

__global__ __launch_bounds__(256) void prepass_kernel(
    TJob j0, TJob j1, TJob j2, TJob j3, TJob j4,
    const float* __restrict__ csrc, __half* __restrict__ cdst, int ctile0)
{
    const int bid = blockIdx.x;
    if (bid >= ctile0) {
        // copy-convert job: each block handles 2048 float4 (32 KB src)
        const float4* s4 = (const float4*)csrc;
        size_t base = (size_t)(bid - ctile0) * 2048 + threadIdx.x;
#pragma unroll
        for (int it = 0; it < 8; it++) {
            size_t i = base + it * 256;
            float4 v = s4[i];
            ((__half2*)cdst)[2*i]     = __floats2half2_rn(v.x, v.y);
            ((__half2*)cdst)[2*i + 1] = __floats2half2_rn(v.z, v.w);
        }
        return;
    }
    __shared__ float t[32][66];
    TJob j;
    if      (bid < j1.tile0) j = j0;
    else if (bid < j2.tile0) j = j1;
    else if (bid < j3.tile0) j = j2;
    else if (bid < j4.tile0) j = j3;
    else                     j = j4;
    const int t_local = bid - j.tile0;
    const int rtiles  = j.R >> 6;
    const int tr = t_local % rtiles;
    const int tcb = t_local / rtiles;
    const int rbase = tr * 64, cbase = tcb * 32;
    const int tx = threadIdx.x & 31, ty = threadIdx.x >> 5;

#pragma unroll
    for (int it = 0; it < 8; it++) {
        int r = ty + it*8;
        t[tx][r] = j.src[(size_t)(rbase + r)*j.C + cbase + tx];
    }
    __syncthreads();
#pragma unroll
    for (int jj = 0; jj < 4; jj++) {
        int c = ty + jj*8;
        float2 v = *(float2*)&t[c][2*tx];
        *(__half2*)&j.dst[(size_t)(cbase + c)*j.R + rbase + 2*tx] =
            __floats2half2_rn(v.x, v.y);
    }
}

// ---------------- fp16 GEMM common ----------------
#define HS 3
#define HBK 64
#define HSTR 72
#define H_TILE_BYTES (128*HSTR*2)
#define H_SMEM (2*HS*H_TILE_BYTES)

// ---------------- single-job fp16 GEMM (templated output, split epilogue) ----------------
template <typename TOut>
__global__ __launch_bounds__(256, 2) void h16_gemm(
    const __half* __restrict__ A, const __half* __restrict__ Bt,
    TOut* __restrict__ C, int M, int N, int K, int ldc,
    TOut* __restrict__ C2, int ldc2, int nsplit)
{
    extern __shared__ char hsm[];
    const uint32_t smb = smem_u32(hsm);
    const __half* As_h = (const __half*)hsm;
    const __half* Bs_h = (const __half*)(hsm + HS*H_TILE_BYTES);

    const int tid  = threadIdx.x;
    const int lane = tid & 31;
    const int warp = tid >> 5;
    const int wm0  = (warp >> 2) * 64;
    const int wn0  = (warp & 3) * 32;
    const int gr   = lane >> 2;
    const int tc   = lane & 3;

    const int bm = blockIdx.y * 128;
    const int bn = blockIdx.x * 128;

    float acc[4][4][4];
#pragma unroll
    for (int mt = 0; mt < 4; mt++)
#pragma unroll
        for (int nt = 0; nt < 4; nt++)
#pragma unroll
            for (int r = 0; r < 4; r++) acc[mt][nt][r] = 0.0f;

    const int r0 = tid >> 3;
    const int ch = tid & 7;
    const __half* Asrc[4]; const __half* Bsrc[4];
    uint32_t soff[4];
#pragma unroll
    for (int i = 0; i < 4; i++) {
        const int rr = r0 + 32*i;
        Asrc[i] = A + (size_t)(bm + rr)*K + ch*8;
        int nr = bn + rr; if (nr > N-1) nr = N-1;
        Bsrc[i] = Bt + (size_t)nr*K + ch*8;
        soff[i] = (uint32_t)(rr*144 + ch*16);
    }
    const uint32_t a_base = smb;
    const uint32_t b_base = smb + HS*H_TILE_BYTES;

    const int ntiles = K >> 6;

    auto issue_stage = [&](int t) {
        const int kg = t * HBK;
        const uint32_t as = a_base + (t % HS) * H_TILE_BYTES;
        const uint32_t bs = b_base + (t % HS) * H_TILE_BYTES;
#pragma unroll
        for (int i = 0; i < 4; i++) CP_ASYNC16(as + soff[i], Asrc[i] + kg);
#pragma unroll
        for (int i = 0; i < 4; i++) CP_ASYNC16(bs + soff[i], Bsrc[i] + kg);
    };

    issue_stage(0); CP_COMMIT();
    issue_stage(1); CP_COMMIT();

    for (int kt = 0; kt < ntiles; kt++) {
        CP_WAIT1();
        __syncthreads();
        if (kt + 2 < ntiles) issue_stage(kt + 2);
        CP_COMMIT();

        const __half* At  = As_h + (kt % HS) * (128*HSTR);
        const __half* Bts = Bs_h + (kt % HS) * (128*HSTR);
#pragma unroll
        for (int ks = 0; ks < 4; ks++) {
            const int k0 = ks * 16;
            uint32_t af[4][4], bf[4][2];
#pragma unroll
            for (int mt = 0; mt < 4; mt++) {
                const int row = wm0 + mt*16 + gr;
                af[mt][0] = *(const uint32_t*)(At + row*HSTR     + k0 + 2*tc);
                af[mt][1] = *(const uint32_t*)(At + (row+8)*HSTR + k0 + 2*tc);
                af[mt][2] = *(const uint32_t*)(At + row*HSTR     + k0 + 8 + 2*tc);
                af[mt][3] = *(const uint32_t*)(At + (row+8)*HSTR + k0 + 8 + 2*tc);
            }
#pragma unroll
            for (int nt = 0; nt < 4; nt++) {
                const int cr = wn0 + nt*8 + gr;
                bf[nt][0] = *(const uint32_t*)(Bts + cr*HSTR + k0 + 2*tc);
                bf[nt][1] = *(const uint32_t*)(Bts + cr*HSTR + k0 + 8 + 2*tc);
            }
#pragma unroll
            for (int mt = 0; mt < 4; mt++)
#pragma unroll
                for (int nt = 0; nt < 4; nt++)
                    MMA_F16(acc[mt][nt], af[mt][0], af[mt][1], af[mt][2], af[mt][3],
                            bf[nt][0], bf[nt][1]);
        }
    }

#pragma unroll
    for (int mt = 0; mt < 4; mt++) {
        const int row0 = bm + wm0 + mt * 16 + gr;
#pragma unroll
        for (int nt = 0; nt < 4; nt++) {
            const int col = bn + wn0 + nt * 8 + tc * 2;
            if (col >= N) continue;
            TOut* dst;
            size_t idx;
            int ld;
            if (col < nsplit) { dst = C;  ld = ldc;  idx = (size_t)row0*ldc  + col; }
            else              { dst = C2; ld = ldc2; idx = (size_t)row0*ldc2 + (col - nsplit); }
            const size_t idx2 = idx + (size_t)8 * ld;
            if constexpr (sizeof(TOut) == 4) {
                *(float2*)&((float*)dst)[idx]  = make_float2(acc[mt][nt][0], acc[mt][nt][1]);
                *(float2*)&((float*)dst)[idx2] = make_float2(acc[mt][nt][2], acc[mt][nt][3]);
            } else {
                *(__half2*)&((__half*)dst)[idx]  = __floats2half2_rn(acc[mt][nt][0], acc[mt][nt][1]);
                *(__half2*)&((__half*)dst)[idx2] = __floats2half2_rn(acc[mt][nt][2], acc[mt][nt][3]);
            }
        }
    }
}

// ---------------- kv GEMM with fused V-transpose epilogue ----------------
__global__ __launch_bounds__(256, 2) void kv_gemm_vt(
    const __half* __restrict__ A, const __half* __restrict__ Bt,
    __half* __restrict__ kvh, __half* __restrict__ vT, int K)
{
    extern __shared__ char hsm[];
    const uint32_t smb = smem_u32(hsm);
    const __half* As_h = (const __half*)hsm;
    const __half* Bs_h = (const __half*)(hsm + HS*H_TILE_BYTES);

    const int tid  = threadIdx.x;
    const int lane = tid & 31;
    const int warp = tid >> 5;
    const int wm0  = (warp >> 2) * 64;
    const int wn0  = (warp & 3) * 32;
    const int gr   = lane >> 2;
    const int tc   = lane & 3;

    const int bm = blockIdx.y * 128;
    const int bn = blockIdx.x * 128;

    float acc[4][4][4];
#pragma unroll
    for (int mt = 0; mt < 4; mt++)
#pragma unroll
        for (int nt = 0; nt < 4; nt++)
#pragma unroll
            for (int r = 0; r < 4; r++) acc[mt][nt][r] = 0.0f;

    const int r0 = tid >> 3;
    const int ch = tid & 7;
    const __half* Asrc[4]; const __half* Bsrc[4];
    uint32_t soff[4];
#pragma unroll
    for (int i = 0; i < 4; i++) {
        const int rr = r0 + 32*i;
        Asrc[i] = A + (size_t)(bm + rr)*K + ch*8;
        Bsrc[i] = Bt + (size_t)(bn + rr)*K + ch*8;
        soff[i] = (uint32_t)(rr*144 + ch*16);
    }
    const uint32_t a_base = smb;
    const uint32_t b_base = smb + HS*H_TILE_BYTES;

    const int ntiles = K >> 6;

    auto issue_stage = [&](int t) {
        const int kg = t * HBK;
        const uint32_t as = a_base + (t % HS) * H_TILE_BYTES;
        const uint32_t bs = b_base + (t % HS) * H_TILE_BYTES;
#pragma unroll
        for (int i = 0; i < 4; i++) CP_ASYNC16(as + soff[i], Asrc[i] + kg);
#pragma unroll
        for (int i = 0; i < 4; i++) CP_ASYNC16(bs + soff[i], Bsrc[i] + kg);
    };

    issue_stage(0); CP_COMMIT();
    issue_stage(1); CP_COMMIT();

    for (int kt = 0; kt < ntiles; kt++) {
        CP_WAIT1();
        __syncthreads();
        if (kt + 2 < ntiles) issue_stage(kt + 2);
        CP_COMMIT();

        const __half* At  = As_h + (kt % HS) * (128*HSTR);
        const __half* Bts = Bs_h + (kt % HS) * (128*HSTR);
#pragma unroll
        for (int ks = 0; ks < 4; ks++) {
            const int k0 = ks * 16;
            uint32_t af[4][4], bf[4][2];
#pragma unroll
            for (int mt = 0; mt < 4; mt++) {
                const int row = wm0 + mt*16 + gr;
                af[mt][0] = *(const uint32_t*)(At + row*HSTR     + k0 + 2*tc);
                af[mt][1] = *(const uint32_t*)(At + (row+8)*HSTR + k0 + 2*tc);
                af[mt][2] = *(const uint32_t*)(At + row*HSTR     + k0 + 8 + 2*tc);
                af[mt][3] = *(const uint32_t*)(At + (row+8)*HSTR + k0 + 8 + 2*tc);
            }
#pragma unroll
            for (int nt = 0; nt < 4; nt++) {
                const int cr = wn0 + nt*8 + gr;
                bf[nt][0] = *(const uint32_t*)(Bts + cr*HSTR + k0 + 2*tc);
                bf[nt][1] = *(const uint32_t*)(Bts + cr*HSTR + k0 + 8 + 2*tc);
            }
#pragma unroll
            for (int mt = 0; mt < 4; mt++)
#pragma unroll
                for (int nt = 0; nt < 4; nt++)
                    MMA_F16(acc[mt][nt], af[mt][0], af[mt][1], af[mt][2], af[mt][3],
                            bf[nt][0], bf[nt][1]);
        }
    }

    if ((bn & 255) == 0) {
#pragma unroll
        for (int mt = 0; mt < 4; mt++) {
            const int row0 = bm + wm0 + mt * 16 + gr;
#pragma unroll
            for (int nt = 0; nt < 4; nt++) {
                const int col = bn + wn0 + nt * 8 + tc * 2;
                *(__half2*)&kvh[(size_t)row0*KV_LD + col] =
                    __floats2half2_rn(acc[mt][nt][0], acc[mt][nt][1]);
                *(__half2*)&kvh[(size_t)(row0 + 8)*KV_LD + col] =
                    __floats2half2_rn(acc[mt][nt][2], acc[mt][nt][3]);
            }
        }
    } else {
        __syncthreads();
        __half* st = (__half*)hsm;
#pragma unroll
        for (int mt = 0; mt < 4; mt++) {
            const int rowl = wm0 + mt * 16 + gr;
#pragma unroll
            for (int nt = 0; nt < 4; nt++) {
                const int coll = wn0 + nt * 8 + tc * 2;
                st[(coll)    *136 + rowl]     = __float2half_rn(acc[mt][nt][0]);
                st[(coll + 1)*136 + rowl]     = __float2half_rn(acc[mt][nt][1]);
                st[(coll)    *136 + rowl + 8] = __float2half_rn(acc[mt][nt][2]);
                st[(coll + 1)*136 + rowl + 8] = __float2half_rn(acc[mt][nt][3]);
            }
        }
        __syncthreads();
        const int hh = bn >> 8;
        __half* vbase = vT + (size_t)hh * DV * NROWS;
#pragma unroll
        for (int i = 0; i < 8; i++) {
            int idx = tid + i * 256;
            int dv = idx >> 4, c8 = (idx & 15) * 8;
            *(uint4*)&vbase[(size_t)dv * NROWS + bm + c8] = *(uint4*)&st[dv*136 + c8];
        }
    }
}

// ---------------- fused RMSNorm(qa) + RMSNorm(ckv) + RoPE(k_pe), vectorized ----------------
__global__ void normfuse_kernel(const __half* __restrict__ qaraw,
                                const __half* __restrict__ ckvall,
                                const float* __restrict__ q_ln,
                                const float* __restrict__ kv_ln,
                                __half* __restrict__ qah,
                                __half* __restrict__ ckvh,
                                __half* __restrict__ kpeh)
{
    __shared__ float red1[256], red2[256];
    const int row = blockIdx.x;
    const int tid = threadIdx.x;
    const __half2* p1 = (const __half2*)(qaraw + (size_t)row*QLORA);
    const __half2* p2 = (const __half2*)(ckvall + (size_t)row*CKV_LD);

    float2 v1[3];
    float ss1 = 0.f;
#pragma unroll
    for (int it = 0; it < 3; it++) {
        v1[it] = __half22float2(p1[tid + it*256]);
        ss1 += v1[it].x*v1[it].x + v1[it].y*v1[it].y;
    }
    float2 v2 = __half22float2(p2[tid]);   // KVLORA/2 = 256: one per thread
    float ss2 = v2.x*v2.x + v2.y*v2.y;

    red1[tid] = ss1; red2[tid] = ss2;
    __syncthreads();
    for (int s = 128; s; s >>= 1) {
        if (tid < s) { red1[tid] += red1[tid + s]; red2[tid] += red2[tid + s]; }
        __syncthreads();
    }
    const float sc1 = rsqrtf(red1[0] / (float)QLORA  + 1e-6f);
    const float sc2 = rsqrtf(red2[0] / (float)KVLORA + 1e-6f);

    __half2* d1 = (__half2*)(qah  + (size_t)row*QLORA);
    __half2* d2 = (__half2*)(ckvh + (size_t)row*KVLORA);
    const float2* w1 = (const float2*)q_ln;
    const float2* w2 = (const float2*)kv_ln;
#pragma unroll
    for (int it = 0; it < 3; it++) {
        float2 w = w1[tid + it*256];
        d1[tid + it*256] = __floats2half2_rn(v1[it].x * sc1 * w.x, v1[it].y * sc1 * w.y);
    }
    {
        float2 w = w2[tid];
        d2[tid] = __floats2half2_rn(v2.x * sc2 * w.x, v2.y * sc2 * w.y);
    }

    if (tid < 32) {
        const int lane = tid;
        const __half* base = (const __half*)p2 + KVLORA;
        float xe = __half2float(base[2*lane]), xo = __half2float(base[2*lane + 1]);
        float inv = 1.0f / powf(10000.0f, (2.0f * (float)lane) / 64.0f);
        float ph = (float)(row % S_LEN) * inv;
        float sn, cs;
        sincosf(ph, &sn, &cs);
        kpeh[(size_t)row*DROPE + lane]      = __float2half_rn(xe*cs - xo*sn);
        kpeh[(size_t)row*DROPE + lane + 32] = __float2half_rn(xo*cs + xe*sn);
    }
}

// ---------------- all-fp16 tensor-core causal flash attention (q-RoPE fused) ----------------
#define FQH 200
#define FVH 40
#define FPH 40
#define BR 128
#define BC 32
#define FLASH_SMEM ((BR*FQH + 2*BC*FQH + 2*DV*FVH + BR*FPH)*2)

__global__ __launch_bounds__(256, 2) void flash_h_kernel(
    const __half* __restrict__ q, const __half* __restrict__ kvh,
    const __half* __restrict__ vT, const __half* __restrict__ kpeh,
    __half* __restrict__ attn)
{
    extern __shared__ __half smh[];
    __half* Qs = smh;
    __half* Ks = Qs + BR*FQH;
    __half* Vt = Ks + 2*BC*FQH;
    __half* Ps = Vt + 2*DV*FVH;

    const int tid  = threadIdx.x;
    const int lane = tid & 31;
    const int warp = tid >> 5;
    const int gr   = lane >> 2;
    const int tc   = lane & 3;
    const int qt = (gridDim.x - 1) - blockIdx.x;
    const int b  = blockIdx.y >> 4;
    const int h  = blockIdx.y & 15;
    const float scale = 0.07216878364870323f; // 1/sqrt(192)

    const int qrow0 = b*S_LEN + qt*BR;
    const int wr0   = warp * 16;

    uint32_t ksm[2], vsm[2];
    ksm[0] = smem_u32(Ks);
    ksm[1] = smem_u32(Ks + BC*FQH);
    vsm[0] = smem_u32(Vt);
    vsm[1] = smem_u32(Vt + DV*FVH);

    const int jmax = 4*qt + 3;

    auto issue_tile = [&](int j, int buf) {
        const int krow0 = b*S_LEN + j*BC;
#pragma unroll
        for (int t = 0; t < 3; t++) {
            int idx = tid + t*256;
            int r = idx / 24, col8 = (idx % 24) * 8;
            const __half* src = (col8 < DNOPE)
                ? kvh + (size_t)(krow0 + r)*KV_LD + h*256 + col8
                : kpeh + (size_t)(krow0 + r)*DROPE + (col8 - DNOPE);
            CP_ASYNC16(ksm[buf] + (uint32_t)(r*FQH + col8)*2, src);
        }
#pragma unroll
        for (int t = 0; t < 2; t++) {
            int idx = tid + t*256;
            int r = idx >> 2, c8 = (idx & 3) * 8;
            const __half* src = vT + (size_t)(h*DV + r)*NROWS + krow0 + c8;
            CP_ASYNC16(vsm[buf] + (uint32_t)(r*FVH + c8)*2, src);
        }
    };

    issue_tile(0, 0);
    CP_COMMIT();

#pragma unroll
    for (int t = 0; t < 12; t++) {
        int idx = tid + t*256;
        int r = idx / 24, c = idx % 24;
        *(uint4*)&Qs[r*FQH + c*8] =
            *(const uint4*)(q + (size_t)(qrow0 + r)*Q_LD + h*DQ + c*8);
    }
    __syncthreads();

    // q-RoPE in smem
    {
        const float inv = 1.0f / powf(10000.0f, (2.0f * (float)lane) / 64.0f);
#pragma unroll
        for (int it = 0; it < 16; it++) {
            const int r = it*8 + warp;
            __half* base = Qs + r*FQH + DNOPE;
            float xe = __half2float(base[2*lane]);
            float xo = __half2float(base[2*lane + 1]);
            float ph = (float)(qt*BR + r) * inv;
            float sn, cs;
            sincosf(ph, &sn, &cs);
            __syncwarp();
            base[lane]      = __float2half_rn(xe*cs - xo*sn);
            base[lane + 32] = __float2half_rn(xo*cs + xe*sn);
            __syncwarp();
        }
    }

    float m0 = -INFINITY, m1 = -INFINITY, l0 = 0.f, l1 = 0.f;
    float o[16][4];
#pragma unroll
    for (int nt = 0; nt < 16; nt++)
#pragma unroll
        for (int r = 0; r < 4; r++) o[nt][r] = 0.f;

    for (int j = 0; j <= jmax; j++) {
        __syncthreads();
        if (j + 1 <= jmax) issue_tile(j + 1, (j + 1) & 1);
        CP_COMMIT();
        CP_WAIT1();
        __syncthreads();

        const int off = j*BC - qt*BR;
        if (off > wr0 + 15) continue;
        const bool needMask = (off + BC - 1 > wr0);

        const __half* Ksb = Ks + (j & 1)*BC*FQH;
        const __half* Vtb = Vt + (j & 1)*DV*FVH;

        float accS[4][4];
#pragma unroll
        for (int nt = 0; nt < 4; nt++)
#pragma unroll
            for (int r = 0; r < 4; r++) accS[nt][r] = 0.f;

#pragma unroll
        for (int k = 0; k < 12; k++) {
            const int k0 = k * 16;
            uint32_t a0 = *(const uint32_t*)(Qs + (wr0 + gr)*FQH     + k0 + 2*tc);
            uint32_t a1 = *(const uint32_t*)(Qs + (wr0 + gr + 8)*FQH + k0 + 2*tc);
            uint32_t a2 = *(const uint32_t*)(Qs + (wr0 + gr)*FQH     + k0 + 8 + 2*tc);
            uint32_t a3 = *(const uint32_t*)(Qs + (wr0 + gr + 8)*FQH + k0 + 8 + 2*tc);
#pragma unroll
            for (int nt = 0; nt < 4; nt++) {
                uint32_t b0 = *(const uint32_t*)(Ksb + (nt*8 + gr)*FQH + k0 + 2*tc);
                uint32_t b1 = *(const uint32_t*)(Ksb + (nt*8 + gr)*FQH + k0 + 8 + 2*tc);
                MMA_F16(accS[nt], a0, a1, a2, a3, b0, b1);
            }
        }

        if (needMask) {
            const int r0 = wr0 + gr, r1 = r0 + 8;
#pragma unroll
            for (int nt = 0; nt < 4; nt++) {
                const int c0 = nt*8 + 2*tc + off;
                accS[nt][0] = (c0     <= r0) ? accS[nt][0]*scale : -INFINITY;
                accS[nt][1] = (c0 + 1 <= r0) ? accS[nt][1]*scale : -INFINITY;
                accS[nt][2] = (c0     <= r1) ? accS[nt][2]*scale : -INFINITY;
                accS[nt][3] = (c0 + 1 <= r1) ? accS[nt][3]*scale : -INFINITY;
            }
        } else {
#pragma unroll
            for (int nt = 0; nt < 4; nt++)
#pragma unroll
                for (int r = 0; r < 4; r++) accS[nt][r] *= scale;
        }

        float rm0 = -INFINITY, rm1 = -INFINITY;
#pragma unroll
        for (int nt = 0; nt < 4; nt++) {
            rm0 = fmaxf(rm0, fmaxf(accS[nt][0], accS[nt][1]));
            rm1 = fmaxf(rm1, fmaxf(accS[nt][2], accS[nt][3]));
        }
        rm0 = fmaxf(rm0, __shfl_xor_sync(0xffffffffu, rm0, 1));
        rm0 = fmaxf(rm0, __shfl_xor_sync(0xffffffffu, rm0, 2));
        rm1 = fmaxf(rm1, __shfl_xor_sync(0xffffffffu, rm1, 1));
        rm1 = fmaxf(rm1, __shfl_xor_sync(0xffffffffu, rm1, 2));

        const float mn0 = fmaxf(m0, rm0), mn1 = fmaxf(m1, rm1);
        const float al0 = __expf(m0 - mn0), al1 = __expf(m1 - mn1);
        m0 = mn0; m1 = mn1;

        float rs0 = 0.f, rs1 = 0.f;
#pragma unroll
        for (int nt = 0; nt < 4; nt++) {
            float p0 = __expf(accS[nt][0] - mn0);
            float p1 = __expf(accS[nt][1] - mn0);
            float p2 = __expf(accS[nt][2] - mn1);
            float p3 = __expf(accS[nt][3] - mn1);
            rs0 += p0 + p1; rs1 += p2 + p3;
            const int c0 = nt*8 + 2*tc;
            *(__half2*)&Ps[(wr0 + gr)*FPH + c0]     = __floats2half2_rn(p0, p1);
            *(__half2*)&Ps[(wr0 + gr + 8)*FPH + c0] = __floats2half2_rn(p2, p3);
        }
        rs0 += __shfl_xor_sync(0xffffffffu, rs0, 1);
        rs0 += __shfl_xor_sync(0xffffffffu, rs0, 2);
        rs1 += __shfl_xor_sync(0xffffffffu, rs1, 1);
        rs1 += __shfl_xor_sync(0xffffffffu, rs1, 2);
        l0 = l0*al0 + rs0;
        l1 = l1*al1 + rs1;

#pragma unroll
        for (int nt = 0; nt < 16; nt++) {
            o[nt][0] *= al0; o[nt][1] *= al0;
            o[nt][2] *= al1; o[nt][3] *= al1;
        }
        __syncwarp();

#pragma unroll
        for (int k = 0; k < 2; k++) {
            const int k0 = k * 16;
            uint32_t a0 = *(const uint32_t*)(Ps + (wr0 + gr)*FPH     + k0 + 2*tc);
            uint32_t a1 = *(const uint32_t*)(Ps + (wr0 + gr + 8)*FPH + k0 + 2*tc);
            uint32_t a2 = *(const uint32_t*)(Ps + (wr0 + gr)*FPH     + k0 + 8 + 2*tc);
            uint32_t a3 = *(const uint32_t*)(Ps + (wr0 + gr + 8)*FPH + k0 + 8 + 2*tc);
#pragma unroll
            for (int nt = 0; nt < 16; nt++) {
                uint32_t b0 = *(const uint32_t*)(Vtb + (nt*8 + gr)*FVH + k0 + 2*tc);
                uint32_t b1 = *(const uint32_t*)(Vtb + (nt*8 + gr)*FVH + k0 + 8 + 2*tc);
                MMA_F16(o[nt], a0, a1, a2, a3, b0, b1);
            }
        }
    }

    const float il0 = 1.0f / l0, il1 = 1.0f / l1;
    const int row0 = qrow0 + wr0 + gr;
#pragma unroll
    for (int nt = 0; nt < 16; nt++) {
        const int col = h*DV + nt*8 + 2*tc;
        *(__half2*)&attn[(size_t)row0*ATTN_LD + col] =
            __floats2half2_rn(o[nt][0]*il0, o[nt][1]*il0);
        *(__half2*)&attn[(size_t)(row0 + 8)*ATTN_LD + col] =
            __floats2half2_rn(o[nt][2]*il1, o[nt][3]*il1);
    }
}

// ---------------- launch ----------------
extern "C" void kernel_launch(void* const* d_in, const int* in_sizes, int n_in,
                              void* d_out, int out_size)
{
    const float* hid    = (const float*)d_in[0];
    const float* w_dq   = (const float*)d_in[1];
    const float* q_ln   = (const float*)d_in[2];
    const float* w_uq   = (const float*)d_in[3];
    const float* kv_a_w = (const float*)d_in[4];
    const float* kv_ln  = (const float*)d_in[5];
    const float* kv_b_w = (const float*)d_in[6];
    const float* o_w    = (const float*)d_in[7];
    float* out = (float*)d_out;

    __half *hidh, *qaraw, *ckvall, *qah, *ckvh, *qh, *kvh, *vTh, *kpeh, *attnh;
    __half *wAT, *wuqT, *kvbT, *owT;
    cudaGetSymbolAddress((void**)&hidh,  g_hidh);
    cudaGetSymbolAddress((void**)&qaraw, g_qaraw);
    cudaGetSymbolAddress((void**)&ckvall,g_ckvall);
    cudaGetSymbolAddress((void**)&qah,   g_qah);
    cudaGetSymbolAddress((void**)&ckvh,  g_ckvh);
    cudaGetSymbolAddress((void**)&qh,    g_qh);
    cudaGetSymbolAddress((void**)&kvh,   g_kvh);
    cudaGetSymbolAddress((void**)&vTh,   g_vTh);
    cudaGetSymbolAddress((void**)&kpeh,  g_kpeh);
    cudaGetSymbolAddress((void**)&attnh, g_attnh);
    cudaGetSymbolAddress((void**)&wAT,   g_wAT);
    cudaGetSymbolAddress((void**)&wuqT,  g_wuqT);
    cudaGetSymbolAddress((void**)&kvbT,  g_kvbT);
    cudaGetSymbolAddress((void**)&owT,   g_owT);

    cudaFuncSetAttribute(flash_h_kernel, cudaFuncAttributeMaxDynamicSharedMemorySize, FLASH_SMEM);
    cudaFuncSetAttribute(h16_gemm<float>, cudaFuncAttributeMaxDynamicSharedMemorySize, H_SMEM);
    cudaFuncSetAttribute(h16_gemm<__half>, cudaFuncAttributeMaxDynamicSharedMemorySize, H_SMEM);
    cudaFuncSetAttribute(kv_gemm_vt, cudaFuncAttributeMaxDynamicSharedMemorySize, H_SMEM);

    // pre-pass: 5 weight transposes + hidden f32->f16 in ONE launch
    {
        TJob j0 = { w_dq,   wAT,                          HIDDEN, QLORA,  0 };
        int t0 = (HIDDEN/64)*(QLORA/32);
        TJob j1 = { kv_a_w, wAT + (size_t)QLORA*HIDDEN,   HIDDEN, CKV_LD, t0 };
        int t1 = t0 + (HIDDEN/64)*(CKV_LD/32);
        TJob j2 = { w_uq,   wuqT,                         QLORA,  Q_LD,   t1 };
        int t2 = t1 + (QLORA/64)*(Q_LD/32);
        TJob j3 = { kv_b_w, kvbT,                         KVLORA, KV_LD,  t2 };
        int t3 = t2 + (KVLORA/64)*(KV_LD/32);
        TJob j4 = { o_w,    owT,                          ATTN_LD, HIDDEN, t3 };
        int t4 = t3 + (ATTN_LD/64)*(HIDDEN/32);
        int ctiles = (NROWS*HIDDEN/4) / 2048;   // 1024 copy blocks
        prepass_kernel<<<t4 + ctiles, 256>>>(j0, j1, j2, j3, j4, hid, hidh, t4);
    }

    // fused [q_a | ckv_pe] = hidden @ [w_dq | kv_a_w]  [4096, 2112] k=2048 (half, split)
    h16_gemm<__half><<<dim3((NFUSE+127)/128, NROWS/128), 256, H_SMEM>>>(
        hidh, wAT, qaraw, NROWS, NFUSE, HIDDEN, QLORA, ckvall, CKV_LD, QLORA);
    // fused RMSNorm(qa) + RMSNorm(ckv) + RoPE(k_pe)
    normfuse_kernel<<<NROWS, 256>>>(qaraw, ckvall, q_ln, kv_ln, qah, ckvh, kpeh);
    // q = q_a_ln @ w_uq          [4096,3072] k=1536 (half out, rope in flash)
    h16_gemm<__half><<<dim3(Q_LD/128, NROWS/128), 256, H_SMEM>>>(
        qah, wuqT, qh, NROWS, Q_LD, QLORA, Q_LD, (__half*)nullptr, 0, 1<<30);
    // kv = ckv_ln @ kv_b_w  [4096,4096] k=512: nope->kvh, V->vT (fused transpose)
    kv_gemm_vt<<<dim3(KV_LD/128, NROWS/128), 256, H_SMEM>>>(ckvh, kvbT, kvh, vTh, KVLORA);
    // all-fp16 causal flash attention (q-RoPE in-kernel) -> attnh
    flash_h_kernel<<<dim3(S_LEN/BR, BATCH*NH), 256, FLASH_SMEM>>>(qh, kvh, vTh, kpeh, attnh);
    // out = attn @ o_w  [4096,2048] k=2048 (fp32 out)
    h16_gemm<float><<<dim3(HIDDEN/128, NROWS/128), 256, H_SMEM>>>(
        attnh, owT, out, NROWS, HIDDEN, ATTN_LD, HIDDEN, (float*)nullptr, 0, 1<<30);
}

// round 17
// speedup vs baseline: 1.1637x; 1.0941x over previous
#include <cuda_runtime.h>
#include <cuda_fp16.h>
#include <math.h>
#include <stdint.h>

// ---------------- problem constants ----------------
#define S_LEN   2048
#define BATCH   2
#define HIDDEN  2048
#define NH      16
#define QLORA   1536
#define KVLORA  512
#define DNOPE   128
#define DROPE   64
#define DV      128
#define DQ      192           // DNOPE + DROPE
#define NROWS   (BATCH*S_LEN) // 4096
#define CKV_LD  (KVLORA + DROPE) // 576
#define KV_LD   (NH*(DNOPE+DV))  // 4096
#define Q_LD    (NH*DQ)          // 3072
#define ATTN_LD (NH*DV)          // 2048
#define NFUSE   (QLORA + CKV_LD) // 2112

// ---------------- scratch (device globals; no runtime alloc) ----------------
__device__ __half g_hidh  [(size_t)NROWS*HIDDEN];
__device__ __half g_qaraw [(size_t)NROWS*QLORA];
__device__ __half g_ckvall[(size_t)NROWS*CKV_LD];
__device__ __half g_qah   [(size_t)NROWS*QLORA];
__device__ __half g_ckvh  [(size_t)NROWS*KVLORA];
__device__ __half g_qh    [(size_t)NROWS*Q_LD];     // q (half, UN-roped; rope in flash)
__device__ __half g_kvh   [(size_t)NROWS*KV_LD];    // only nope halves written/read
__device__ __half g_vTh   [(size_t)NH*DV*NROWS];    // V transposed [h][dv][row]
__device__ __half g_kpeh  [(size_t)NROWS*DROPE];
__device__ __half g_attnh [(size_t)NROWS*ATTN_LD];
__device__ __half g_wAT   [(size_t)NFUSE*HIDDEN];
__device__ __half g_wuqT  [(size_t)Q_LD*QLORA];
__device__ __half g_kvbT  [(size_t)KV_LD*KVLORA];
__device__ __half g_owT   [(size_t)HIDDEN*ATTN_LD];

// ---------------- helpers ----------------
#define MMA_F16(acc, a0,a1,a2,a3, b0,b1)                                        \
    asm volatile(                                                               \
        "mma.sync.aligned.m16n8k16.row.col.f32.f16.f16.f32 "                    \
        "{%0,%1,%2,%3}, {%4,%5,%6,%7}, {%8,%9}, {%0,%1,%2,%3};"                 \
        : "+f"(acc[0]), "+f"(acc[1]), "+f"(acc[2]), "+f"(acc[3])                \
        : "r"(a0), "r"(a1), "r"(a2), "r"(a3), "r"(b0), "r"(b1))

#define LDSM_X4(r0,r1,r2,r3, addr)                                              \
    asm volatile("ldmatrix.sync.aligned.m8n8.x4.shared.b16 {%0,%1,%2,%3}, [%4];"\
        : "=r"(r0), "=r"(r1), "=r"(r2), "=r"(r3) : "r"(addr))

#define CP_ASYNC16(dst_u32, src_ptr)                                            \
    asm volatile("cp.async.cg.shared.global [%0], [%1], 16;"                    \
                 :: "r"(dst_u32), "l"(src_ptr))
#define CP_COMMIT() asm volatile("cp.async.commit_group;")
#define CP_WAIT1()  asm volatile("cp.async.wait_group 1;")

__device__ __forceinline__ uint32_t smem_u32(const void* p) {
    uint32_t a;
    asm("{ .reg .u64 t; cvta.to.shared.u64 t, %1; cvt.u32.u64 %0, t; }"
        : "=r"(a) : "l"(p));
    return a;
}

// ---------------- pre-pass: 5 transposes + hidden f32->f16 copy, ONE launch ----------------
struct TJob { const float* src; __half* dst; int R, C, tile0; };

__global__ __launch_bounds__(256) void prepass_kernel(
    TJob j0, TJob j1, TJob j2, TJob j3, TJob j4,
    const float* __restrict__ csrc, __half* __restrict__ cdst, int ctile0)
{
    const int bid = blockIdx.x;
    if (bid >= ctile0) {
        const float4* s4 = (const float4*)csrc;
        size_t base = (size_t)(bid - ctile0) * 2048 + threadIdx.x;
#pragma unroll
        for (int it = 0; it < 8; it++) {
            size_t i = base + it * 256;
            float4 v = s4[i];
            ((__half2*)cdst)[2*i]     = __floats2half2_rn(v.x, v.y);
            ((__half2*)cdst)[2*i + 1] = __floats2half2_rn(v.z, v.w);
        }
        return;
    }
    __shared__ float t[32][66];
    TJob j;
    if      (bid < j1.tile0) j = j0;
    else if (bid < j2.tile0) j = j1;
    else if (bid < j3.tile0) j = j2;
    else if (bid < j4.tile0) j = j3;
    else                     j = j4;
    const int t_local = bid - j.tile0;
    const int rtiles  = j.R >> 6;
    const int tr = t_local % rtiles;
    const int tcb = t_local / rtiles;
    const int rbase = tr * 64, cbase = tcb * 32;
    const int tx = threadIdx.x & 31, ty = threadIdx.x >> 5;

#pragma unroll
    for (int it = 0; it < 8; it++) {
        int r = ty + it*8;
        t[tx][r] = j.src[(size_t)(rbase + r)*j.C + cbase + tx];
    }
    __syncthreads();
#pragma unroll
    for (int jj = 0; jj < 4; jj++) {
        int c = ty + jj*8;
        float2 v = *(float2*)&t[c][2*tx];
        *(__half2*)&j.dst[(size_t)(cbase + c)*j.R + rbase + 2*tx] =
            __floats2half2_rn(v.x, v.y);
    }
}

// ---------------- fp16 GEMM common ----------------
#define HS 3
#define HBK 64
#define HSTR 72
#define H_TILE_BYTES (128*HSTR*2)
#define H_SMEM (2*HS*H_TILE_BYTES)

// ---------------- single-job fp16 GEMM (ldmatrix fragments) ----------------
template <typename TOut>
__global__ __launch_bounds__(256, 2) void h16_gemm(
    const __half* __restrict__ A, const __half* __restrict__ Bt,
    TOut* __restrict__ C, int M, int N, int K, int ldc,
    TOut* __restrict__ C2, int ldc2, int nsplit)
{
    extern __shared__ char hsm[];
    const uint32_t smb = smem_u32(hsm);

    const int tid  = threadIdx.x;
    const int lane = tid & 31;
    const int warp = tid >> 5;
    const int wm0  = (warp >> 2) * 64;
    const int wn0  = (warp & 3) * 32;
    const int gr   = lane >> 2;
    const int tc   = lane & 3;

    const int bm = blockIdx.y * 128;
    const int bn = blockIdx.x * 128;

    float acc[4][4][4];
#pragma unroll
    for (int mt = 0; mt < 4; mt++)
#pragma unroll
        for (int nt = 0; nt < 4; nt++)
#pragma unroll
            for (int r = 0; r < 4; r++) acc[mt][nt][r] = 0.0f;

    const int r0 = tid >> 3;
    const int ch = tid & 7;
    const __half* Asrc[4]; const __half* Bsrc[4];
    uint32_t soff[4];
#pragma unroll
    for (int i = 0; i < 4; i++) {
        const int rr = r0 + 32*i;
        Asrc[i] = A + (size_t)(bm + rr)*K + ch*8;
        int nr = bn + rr; if (nr > N-1) nr = N-1;
        Bsrc[i] = Bt + (size_t)nr*K + ch*8;
        soff[i] = (uint32_t)(rr*144 + ch*16);
    }
    const uint32_t a_base = smb;
    const uint32_t b_base = smb + HS*H_TILE_BYTES;

    // ldmatrix lane offsets (in halves, within tile)
    const int la15 = lane & 15, la7 = lane & 7;
    uint32_t aoff[4], boff[2];
#pragma unroll
    for (int mt = 0; mt < 4; mt++)
        aoff[mt] = (uint32_t)((wm0 + mt*16 + la15)*HSTR + ((lane>>4)&1)*8);
#pragma unroll
    for (int p = 0; p < 2; p++)
        boff[p] = (uint32_t)((wn0 + p*16 + ((lane>>4)&1)*8 + la7)*HSTR + ((lane>>3)&1)*8);

    const int ntiles = K >> 6;

    auto issue_stage = [&](int t) {
        const int kg = t * HBK;
        const uint32_t as = a_base + (t % HS) * H_TILE_BYTES;
        const uint32_t bs = b_base + (t % HS) * H_TILE_BYTES;
#pragma unroll
        for (int i = 0; i < 4; i++) CP_ASYNC16(as + soff[i], Asrc[i] + kg);
#pragma unroll
        for (int i = 0; i < 4; i++) CP_ASYNC16(bs + soff[i], Bsrc[i] + kg);
    };

    issue_stage(0); CP_COMMIT();
    issue_stage(1); CP_COMMIT();

    for (int kt = 0; kt < ntiles; kt++) {
        CP_WAIT1();
        __syncthreads();
        if (kt + 2 < ntiles) issue_stage(kt + 2);
        CP_COMMIT();

        const uint32_t tA = a_base + (kt % HS) * H_TILE_BYTES;
        const uint32_t tB = b_base + (kt % HS) * H_TILE_BYTES;
#pragma unroll
        for (int ks = 0; ks < 4; ks++) {
            const int k0 = ks * 16;
            uint32_t af[4][4], bf[4][2];
#pragma unroll
            for (int mt = 0; mt < 4; mt++)
                LDSM_X4(af[mt][0], af[mt][1], af[mt][2], af[mt][3],
                        tA + (aoff[mt] + k0)*2);
#pragma unroll
            for (int p = 0; p < 2; p++)
                LDSM_X4(bf[2*p][0], bf[2*p][1], bf[2*p+1][0], bf[2*p+1][1],
                        tB + (boff[p] + k0)*2);
#pragma unroll
            for (int mt = 0; mt < 4; mt++)
#pragma unroll
                for (int nt = 0; nt < 4; nt++)
                    MMA_F16(acc[mt][nt], af[mt][0], af[mt][1], af[mt][2], af[mt][3],
                            bf[nt][0], bf[nt][1]);
        }
    }

#pragma unroll
    for (int mt = 0; mt < 4; mt++) {
        const int row0 = bm + wm0 + mt * 16 + gr;
#pragma unroll
        for (int nt = 0; nt < 4; nt++) {
            const int col = bn + wn0 + nt * 8 + tc * 2;
            if (col >= N) continue;
            TOut* dst;
            size_t idx;
            int ld;
            if (col < nsplit) { dst = C;  ld = ldc;  idx = (size_t)row0*ldc  + col; }
            else              { dst = C2; ld = ldc2; idx = (size_t)row0*ldc2 + (col - nsplit); }
            const size_t idx2 = idx + (size_t)8 * ld;
            if constexpr (sizeof(TOut) == 4) {
                *(float2*)&((float*)dst)[idx]  = make_float2(acc[mt][nt][0], acc[mt][nt][1]);
                *(float2*)&((float*)dst)[idx2] = make_float2(acc[mt][nt][2], acc[mt][nt][3]);
            } else {
                *(__half2*)&((__half*)dst)[idx]  = __floats2half2_rn(acc[mt][nt][0], acc[mt][nt][1]);
                *(__half2*)&((__half*)dst)[idx2] = __floats2half2_rn(acc[mt][nt][2], acc[mt][nt][3]);
            }
        }
    }
}

// ---------------- kv GEMM with fused V-transpose epilogue (ldmatrix fragments) ----------------
__global__ __launch_bounds__(256, 2) void kv_gemm_vt(
    const __half* __restrict__ A, const __half* __restrict__ Bt,
    __half* __restrict__ kvh, __half* __restrict__ vT, int K)
{
    extern __shared__ char hsm[];
    const uint32_t smb = smem_u32(hsm);

    const int tid  = threadIdx.x;
    const int lane = tid & 31;
    const int warp = tid >> 5;
    const int wm0  = (warp >> 2) * 64;
    const int wn0  = (warp & 3) * 32;
    const int gr   = lane >> 2;
    const int tc   = lane & 3;

    const int bm = blockIdx.y * 128;
    const int bn = blockIdx.x * 128;

    float acc[4][4][4];
#pragma unroll
    for (int mt = 0; mt < 4; mt++)
#pragma unroll
        for (int nt = 0; nt < 4; nt++)
#pragma unroll
            for (int r = 0; r < 4; r++) acc[mt][nt][r] = 0.0f;

    const int r0 = tid >> 3;
    const int ch = tid & 7;
    const __half* Asrc[4]; const __half* Bsrc[4];
    uint32_t soff[4];
#pragma unroll
    for (int i = 0; i < 4; i++) {
        const int rr = r0 + 32*i;
        Asrc[i] = A + (size_t)(bm + rr)*K + ch*8;
        Bsrc[i] = Bt + (size_t)(bn + rr)*K + ch*8;
        soff[i] = (uint32_t)(rr*144 + ch*16);
    }
    const uint32_t a_base = smb;
    const uint32_t b_base = smb + HS*H_TILE_BYTES;

    const int la15 = lane & 15, la7 = lane & 7;
    uint32_t aoff[4], boff[2];
#pragma unroll
    for (int mt = 0; mt < 4; mt++)
        aoff[mt] = (uint32_t)((wm0 + mt*16 + la15)*HSTR + ((lane>>4)&1)*8);
#pragma unroll
    for (int p = 0; p < 2; p++)
        boff[p] = (uint32_t)((wn0 + p*16 + ((lane>>4)&1)*8 + la7)*HSTR + ((lane>>3)&1)*8);

    const int ntiles = K >> 6;

    auto issue_stage = [&](int t) {
        const int kg = t * HBK;
        const uint32_t as = a_base + (t % HS) * H_TILE_BYTES;
        const uint32_t bs = b_base + (t % HS) * H_TILE_BYTES;
#pragma unroll
        for (int i = 0; i < 4; i++) CP_ASYNC16(as + soff[i], Asrc[i] + kg);
#pragma unroll
        for (int i = 0; i < 4; i++) CP_ASYNC16(bs + soff[i], Bsrc[i] + kg);
    };

    issue_stage(0); CP_COMMIT();
    issue_stage(1); CP_COMMIT();

    for (int kt = 0; kt < ntiles; kt++) {
        CP_WAIT1();
        __syncthreads();
        if (kt + 2 < ntiles) issue_stage(kt + 2);
        CP_COMMIT();

        const uint32_t tA = a_base + (kt % HS) * H_TILE_BYTES;
        const uint32_t tB = b_base + (kt % HS) * H_TILE_BYTES;
#pragma unroll
        for (int ks = 0; ks < 4; ks++) {
            const int k0 = ks * 16;
            uint32_t af[4][4], bf[4][2];
#pragma unroll
            for (int mt = 0; mt < 4; mt++)
                LDSM_X4(af[mt][0], af[mt][1], af[mt][2], af[mt][3],
                        tA + (aoff[mt] + k0)*2);
#pragma unroll
            for (int p = 0; p < 2; p++)
                LDSM_X4(bf[2*p][0], bf[2*p][1], bf[2*p+1][0], bf[2*p+1][1],
                        tB + (boff[p] + k0)*2);
#pragma unroll
            for (int mt = 0; mt < 4; mt++)
#pragma unroll
                for (int nt = 0; nt < 4; nt++)
                    MMA_F16(acc[mt][nt], af[mt][0], af[mt][1], af[mt][2], af[mt][3],
                            bf[nt][0], bf[nt][1]);
        }
    }

    if ((bn & 255) == 0) {
#pragma unroll
        for (int mt = 0; mt < 4; mt++) {
            const int row0 = bm + wm0 + mt * 16 + gr;
#pragma unroll
            for (int nt = 0; nt < 4; nt++) {
                const int col = bn + wn0 + nt * 8 + tc * 2;
                *(__half2*)&kvh[(size_t)row0*KV_LD + col] =
                    __floats2half2_rn(acc[mt][nt][0], acc[mt][nt][1]);
                *(__half2*)&kvh[(size_t)(row0 + 8)*KV_LD + col] =
                    __floats2half2_rn(acc[mt][nt][2], acc[mt][nt][3]);
            }
        }
    } else {
        __syncthreads();
        __half* st = (__half*)hsm;
#pragma unroll
        for (int mt = 0; mt < 4; mt++) {
            const int rowl = wm0 + mt * 16 + gr;
#pragma unroll
            for (int nt = 0; nt < 4; nt++) {
                const int coll = wn0 + nt * 8 + tc * 2;
                st[(coll)    *136 + rowl]     = __float2half_rn(acc[mt][nt][0]);
                st[(coll + 1)*136 + rowl]     = __float2half_rn(acc[mt][nt][1]);
                st[(coll)    *136 + rowl + 8] = __float2half_rn(acc[mt][nt][2]);
                st[(coll + 1)*136 + rowl + 8] = __float2half_rn(acc[mt][nt][3]);
            }
        }
        __syncthreads();
        const int hh = bn >> 8;
        __half* vbase = vT + (size_t)hh * DV * NROWS;
#pragma unroll
        for (int i = 0; i < 8; i++) {
            int idx = tid + i * 256;
            int dv = idx >> 4, c8 = (idx & 15) * 8;
            *(uint4*)&vbase[(size_t)dv * NROWS + bm + c8] = *(uint4*)&st[dv*136 + c8];
        }
    }
}

// ---------------- fused RMSNorm(qa) + RMSNorm(ckv) + RoPE(k_pe), vectorized ----------------
__global__ void normfuse_kernel(const __half* __restrict__ qaraw,
                                const __half* __restrict__ ckvall,
                                const float* __restrict__ q_ln,
                                const float* __restrict__ kv_ln,
                                __half* __restrict__ qah,
                                __half* __restrict__ ckvh,
                                __half* __restrict__ kpeh)
{
    __shared__ float red1[256], red2[256];
    const int row = blockIdx.x;
    const int tid = threadIdx.x;
    const __half2* p1 = (const __half2*)(qaraw + (size_t)row*QLORA);
    const __half2* p2 = (const __half2*)(ckvall + (size_t)row*CKV_LD);

    float2 v1[3];
    float ss1 = 0.f;
#pragma unroll
    for (int it = 0; it < 3; it++) {
        v1[it] = __half22float2(p1[tid + it*256]);
        ss1 += v1[it].x*v1[it].x + v1[it].y*v1[it].y;
    }
    float2 v2 = __half22float2(p2[tid]);
    float ss2 = v2.x*v2.x + v2.y*v2.y;

    red1[tid] = ss1; red2[tid] = ss2;
    __syncthreads();
    for (int s = 128; s; s >>= 1) {
        if (tid < s) { red1[tid] += red1[tid + s]; red2[tid] += red2[tid + s]; }
        __syncthreads();
    }
    const float sc1 = rsqrtf(red1[0] / (float)QLORA  + 1e-6f);
    const float sc2 = rsqrtf(red2[0] / (float)KVLORA + 1e-6f);

    __half2* d1 = (__half2*)(qah  + (size_t)row*QLORA);
    __half2* d2 = (__half2*)(ckvh + (size_t)row*KVLORA);
    const float2* w1 = (const float2*)q_ln;
    const float2* w2 = (const float2*)kv_ln;
#pragma unroll
    for (int it = 0; it < 3; it++) {
        float2 w = w1[tid + it*256];
        d1[tid + it*256] = __floats2half2_rn(v1[it].x * sc1 * w.x, v1[it].y * sc1 * w.y);
    }
    {
        float2 w = w2[tid];
        d2[tid] = __floats2half2_rn(v2.x * sc2 * w.x, v2.y * sc2 * w.y);
    }

    if (tid < 32) {
        const int lane = tid;
        const __half* base = (const __half*)p2 + KVLORA;
        float xe = __half2float(base[2*lane]), xo = __half2float(base[2*lane + 1]);
        float inv = 1.0f / powf(10000.0f, (2.0f * (float)lane) / 64.0f);
        float ph = (float)(row % S_LEN) * inv;
        float sn, cs;
        sincosf(ph, &sn, &cs);
        kpeh[(size_t)row*DROPE + lane]      = __float2half_rn(xe*cs - xo*sn);
        kpeh[(size_t)row*DROPE + lane + 32] = __float2half_rn(xo*cs + xe*sn);
    }
}

// ---------------- all-fp16 tensor-core causal flash attention (q-RoPE fused) ----------------
#define FQH 200
#define FVH 40
#define FPH 40
#define BR 128
#define BC 32
#define FLASH_SMEM ((BR*FQH + 2*BC*FQH + 2*DV*FVH + BR*FPH)*2)

__global__ __launch_bounds__(256, 2) void flash_h_kernel(
    const __half* __restrict__ q, const __half* __restrict__ kvh,
    const __half* __restrict__ vT, const __half* __restrict__ kpeh,
    __half* __restrict__ attn)
{
    extern __shared__ __half smh[];
    __half* Qs = smh;
    __half* Ks = Qs + BR*FQH;
    __half* Vt = Ks + 2*BC*FQH;
    __half* Ps = Vt + 2*DV*FVH;

    const int tid  = threadIdx.x;
    const int lane = tid & 31;
    const int warp = tid >> 5;
    const int gr   = lane >> 2;
    const int tc   = lane & 3;
    const int qt = (gridDim.x - 1) - blockIdx.x;
    const int b  = blockIdx.y >> 4;
    const int h  = blockIdx.y & 15;
    const float scale = 0.07216878364870323f; // 1/sqrt(192)

    const int qrow0 = b*S_LEN + qt*BR;
    const int wr0   = warp * 16;

    uint32_t ksm[2], vsm[2];
    ksm[0] = smem_u32(Ks);
    ksm[1] = smem_u32(Ks + BC*FQH);
    vsm[0] = smem_u32(Vt);
    vsm[1] = smem_u32(Vt + DV*FVH);

    const int jmax = 4*qt + 3;

    auto issue_tile = [&](int j, int buf) {
        const int krow0 = b*S_LEN + j*BC;
#pragma unroll
        for (int t = 0; t < 3; t++) {
            int idx = tid + t*256;
            int r = idx / 24, col8 = (idx % 24) * 8;
            const __half* src = (col8 < DNOPE)
                ? kvh + (size_t)(krow0 + r)*KV_LD + h*256 + col8
                : kpeh + (size_t)(krow0 + r)*DROPE + (col8 - DNOPE);
            CP_ASYNC16(ksm[buf] + (uint32_t)(r*FQH + col8)*2, src);
        }
#pragma unroll
        for (int t = 0; t < 2; t++) {
            int idx = tid + t*256;
            int r = idx >> 2, c8 = (idx & 3) * 8;
            const __half* src = vT + (size_t)(h*DV + r)*NROWS + krow0 + c8;
            CP_ASYNC16(vsm[buf] + (uint32_t)(r*FVH + c8)*2, src);
        }
    };

    issue_tile(0, 0);
    CP_COMMIT();

#pragma unroll
    for (int t = 0; t < 12; t++) {
        int idx = tid + t*256;
        int r = idx / 24, c = idx % 24;
        *(uint4*)&Qs[r*FQH + c*8] =
            *(const uint4*)(q + (size_t)(qrow0 + r)*Q_LD + h*DQ + c*8);
    }
    __syncthreads();

    // q-RoPE in smem
    {
        const float inv = 1.0f / powf(10000.0f, (2.0f * (float)lane) / 64.0f);
#pragma unroll
        for (int it = 0; it < 16; it++) {
            const int r = it*8 + warp;
            __half* base = Qs + r*FQH + DNOPE;
            float xe = __half2float(base[2*lane]);
            float xo = __half2float(base[2*lane + 1]);
            float ph = (float)(qt*BR + r) * inv;
            float sn, cs;
            sincosf(ph, &sn, &cs);
            __syncwarp();
            base[lane]      = __float2half_rn(xe*cs - xo*sn);
            base[lane + 32] = __float2half_rn(xo*cs + xe*sn);
            __syncwarp();
        }
    }

    float m0 = -INFINITY, m1 = -INFINITY, l0 = 0.f, l1 = 0.f;
    float o[16][4];
#pragma unroll
    for (int nt = 0; nt < 16; nt++)
#pragma unroll
        for (int r = 0; r < 4; r++) o[nt][r] = 0.f;

    for (int j = 0; j <= jmax; j++) {
        __syncthreads();
        if (j + 1 <= jmax) issue_tile(j + 1, (j + 1) & 1);
        CP_COMMIT();
        CP_WAIT1();
        __syncthreads();

        const int off = j*BC - qt*BR;
        if (off > wr0 + 15) continue;
        const bool needMask = (off + BC - 1 > wr0);

        const __half* Ksb = Ks + (j & 1)*BC*FQH;
        const __half* Vtb = Vt + (j & 1)*DV*FVH;

        float accS[4][4];
#pragma unroll
        for (int nt = 0; nt < 4; nt++)
#pragma unroll
            for (int r = 0; r < 4; r++) accS[nt][r] = 0.f;

#pragma unroll
        for (int k = 0; k < 12; k++) {
            const int k0 = k * 16;
            uint32_t a0 = *(const uint32_t*)(Qs + (wr0 + gr)*FQH     + k0 + 2*tc);
            uint32_t a1 = *(const uint32_t*)(Qs + (wr0 + gr + 8)*FQH + k0 + 2*tc);
            uint32_t a2 = *(const uint32_t*)(Qs + (wr0 + gr)*FQH     + k0 + 8 + 2*tc);
            uint32_t a3 = *(const uint32_t*)(Qs + (wr0 + gr + 8)*FQH + k0 + 8 + 2*tc);
#pragma unroll
            for (int nt = 0; nt < 4; nt++) {
                uint32_t b0 = *(const uint32_t*)(Ksb + (nt*8 + gr)*FQH + k0 + 2*tc);
                uint32_t b1 = *(const uint32_t*)(Ksb + (nt*8 + gr)*FQH + k0 + 8 + 2*tc);
                MMA_F16(accS[nt], a0, a1, a2, a3, b0, b1);
            }
        }

        if (needMask) {
            const int r0 = wr0 + gr, r1 = r0 + 8;
#pragma unroll
            for (int nt = 0; nt < 4; nt++) {
                const int c0 = nt*8 + 2*tc + off;
                accS[nt][0] = (c0     <= r0) ? accS[nt][0]*scale : -INFINITY;
                accS[nt][1] = (c0 + 1 <= r0) ? accS[nt][1]*scale : -INFINITY;
                accS[nt][2] = (c0     <= r1) ? accS[nt][2]*scale : -INFINITY;
                accS[nt][3] = (c0 + 1 <= r1) ? accS[nt][3]*scale : -INFINITY;
            }
        } else {
#pragma unroll
            for (int nt = 0; nt < 4; nt++)
#pragma unroll
                for (int r = 0; r < 4; r++) accS[nt][r] *= scale;
        }

        float rm0 = -INFINITY, rm1 = -INFINITY;
#pragma unroll
        for (int nt = 0; nt < 4; nt++) {
            rm0 = fmaxf(rm0, fmaxf(accS[nt][0], accS[nt][1]));
            rm1 = fmaxf(rm1, fmaxf(accS[nt][2], accS[nt][3]));
        }
        rm0 = fmaxf(rm0, __shfl_xor_sync(0xffffffffu, rm0, 1));
        rm0 = fmaxf(rm0, __shfl_xor_sync(0xffffffffu, rm0, 2));
        rm1 = fmaxf(rm1, __shfl_xor_sync(0xffffffffu, rm1, 1));
        rm1 = fmaxf(rm1, __shfl_xor_sync(0xffffffffu, rm1, 2));

        const float mn0 = fmaxf(m0, rm0), mn1 = fmaxf(m1, rm1);
        const float al0 = __expf(m0 - mn0), al1 = __expf(m1 - mn1);
        m0 = mn0; m1 = mn1;

        float rs0 = 0.f, rs1 = 0.f;
#pragma unroll
        for (int nt = 0; nt < 4; nt++) {
            float p0 = __expf(accS[nt][0] - mn0);
            float p1 = __expf(accS[nt][1] - mn0);
            float p2 = __expf(accS[nt][2] - mn1);
            float p3 = __expf(accS[nt][3] - mn1);
            rs0 += p0 + p1; rs1 += p2 + p3;
            const int c0 = nt*8 + 2*tc;
            *(__half2*)&Ps[(wr0 + gr)*FPH + c0]     = __floats2half2_rn(p0, p1);
            *(__half2*)&Ps[(wr0 + gr + 8)*FPH + c0] = __floats2half2_rn(p2, p3);
        }
        rs0 += __shfl_xor_sync(0xffffffffu, rs0, 1);
        rs0 += __shfl_xor_sync(0xffffffffu, rs0, 2);
        rs1 += __shfl_xor_sync(0xffffffffu, rs1, 1);
        rs1 += __shfl_xor_sync(0xffffffffu, rs1, 2);
        l0 = l0*al0 + rs0;
        l1 = l1*al1 + rs1;

#pragma unroll
        for (int nt = 0; nt < 16; nt++) {
            o[nt][0] *= al0; o[nt][1] *= al0;
            o[nt][2] *= al1; o[nt][3] *= al1;
        }
        __syncwarp();

#pragma unroll
        for (int k = 0; k < 2; k++) {
            const int k0 = k * 16;
            uint32_t a0 = *(const uint32_t*)(Ps + (wr0 + gr)*FPH     + k0 + 2*tc);
            uint32_t a1 = *(const uint32_t*)(Ps + (wr0 + gr + 8)*FPH + k0 + 2*tc);
            uint32_t a2 = *(const uint32_t*)(Ps + (wr0 + gr)*FPH     + k0 + 8 + 2*tc);
            uint32_t a3 = *(const uint32_t*)(Ps + (wr0 + gr + 8)*FPH + k0 + 8 + 2*tc);
#pragma unroll
            for (int nt = 0; nt < 16; nt++) {
                uint32_t b0 = *(const uint32_t*)(Vtb + (nt*8 + gr)*FVH + k0 + 2*tc);
                uint32_t b1 = *(const uint32_t*)(Vtb + (nt*8 + gr)*FVH + k0 + 8 + 2*tc);
                MMA_F16(o[nt], a0, a1, a2, a3, b0, b1);
            }
        }
    }

    const float il0 = 1.0f / l0, il1 = 1.0f / l1;
    const int row0 = qrow0 + wr0 + gr;
#pragma unroll
    for (int nt = 0; nt < 16; nt++) {
        const int col = h*DV + nt*8 + 2*tc;
        *(__half2*)&attn[(size_t)row0*ATTN_LD + col] =
            __floats2half2_rn(o[nt][0]*il0, o[nt][1]*il0);
        *(__half2*)&attn[(size_t)(row0 + 8)*ATTN_LD + col] =
            __floats2half2_rn(o[nt][2]*il1, o[nt][3]*il1);
    }
}

// ---------------- launch ----------------
extern "C" void kernel_launch(void* const* d_in, const int* in_sizes, int n_in,
                              void* d_out, int out_size)
{
    const float* hid    = (const float*)d_in[0];
    const float* w_dq   = (const float*)d_in[1];
    const float* q_ln   = (const float*)d_in[2];
    const float* w_uq   = (const float*)d_in[3];
    const float* kv_a_w = (const float*)d_in[4];
    const float* kv_ln  = (const float*)d_in[5];
    const float* kv_b_w = (const float*)d_in[6];
    const float* o_w    = (const float*)d_in[7];
    float* out = (float*)d_out;

    __half *hidh, *qaraw, *ckvall, *qah, *ckvh, *qh, *kvh, *vTh, *kpeh, *attnh;
    __half *wAT, *wuqT, *kvbT, *owT;
    cudaGetSymbolAddress((void**)&hidh,  g_hidh);
    cudaGetSymbolAddress((void**)&qaraw, g_qaraw);
    cudaGetSymbolAddress((void**)&ckvall,g_ckvall);
    cudaGetSymbolAddress((void**)&qah,   g_qah);
    cudaGetSymbolAddress((void**)&ckvh,  g_ckvh);
    cudaGetSymbolAddress((void**)&qh,    g_qh);
    cudaGetSymbolAddress((void**)&kvh,   g_kvh);
    cudaGetSymbolAddress((void**)&vTh,   g_vTh);
    cudaGetSymbolAddress((void**)&kpeh,  g_kpeh);
    cudaGetSymbolAddress((void**)&attnh, g_attnh);
    cudaGetSymbolAddress((void**)&wAT,   g_wAT);
    cudaGetSymbolAddress((void**)&wuqT,  g_wuqT);
    cudaGetSymbolAddress((void**)&kvbT,  g_kvbT);
    cudaGetSymbolAddress((void**)&owT,   g_owT);

    cudaFuncSetAttribute(flash_h_kernel, cudaFuncAttributeMaxDynamicSharedMemorySize, FLASH_SMEM);
    cudaFuncSetAttribute(h16_gemm<float>, cudaFuncAttributeMaxDynamicSharedMemorySize, H_SMEM);
    cudaFuncSetAttribute(h16_gemm<__half>, cudaFuncAttributeMaxDynamicSharedMemorySize, H_SMEM);
    cudaFuncSetAttribute(kv_gemm_vt, cudaFuncAttributeMaxDynamicSharedMemorySize, H_SMEM);

    // pre-pass: 5 weight transposes + hidden f32->f16 in ONE launch
    {
        TJob j0 = { w_dq,   wAT,                          HIDDEN, QLORA,  0 };
        int t0 = (HIDDEN/64)*(QLORA/32);
        TJob j1 = { kv_a_w, wAT + (size_t)QLORA*HIDDEN,   HIDDEN, CKV_LD, t0 };
        int t1 = t0 + (HIDDEN/64)*(CKV_LD/32);
        TJob j2 = { w_uq,   wuqT,                         QLORA,  Q_LD,   t1 };
        int t2 = t1 + (QLORA/64)*(Q_LD/32);
        TJob j3 = { kv_b_w, kvbT,                         KVLORA, KV_LD,  t2 };
        int t3 = t2 + (KVLORA/64)*(KV_LD/32);
        TJob j4 = { o_w,    owT,                          ATTN_LD, HIDDEN, t3 };
        int t4 = t3 + (ATTN_LD/64)*(HIDDEN/32);
        int ctiles = (NROWS*HIDDEN/4) / 2048;
        prepass_kernel<<<t4 + ctiles, 256>>>(j0, j1, j2, j3, j4, hid, hidh, t4);
    }

    // fused [q_a | ckv_pe] = hidden @ [w_dq | kv_a_w]  [4096, 2112] k=2048 (half, split)
    h16_gemm<__half><<<dim3((NFUSE+127)/128, NROWS/128), 256, H_SMEM>>>(
        hidh, wAT, qaraw, NROWS, NFUSE, HIDDEN, QLORA, ckvall, CKV_LD, QLORA);
    // fused RMSNorm(qa) + RMSNorm(ckv) + RoPE(k_pe)
    normfuse_kernel<<<NROWS, 256>>>(qaraw, ckvall, q_ln, kv_ln, qah, ckvh, kpeh);
    // q = q_a_ln @ w_uq          [4096,3072] k=1536 (half out, rope in flash)
    h16_gemm<__half><<<dim3(Q_LD/128, NROWS/128), 256, H_SMEM>>>(
        qah, wuqT, qh, NROWS, Q_LD, QLORA, Q_LD, (__half*)nullptr, 0, 1<<30);
    // kv = ckv_ln @ kv_b_w  [4096,4096] k=512: nope->kvh, V->vT (fused transpose)
    kv_gemm_vt<<<dim3(KV_LD/128, NROWS/128), 256, H_SMEM>>>(ckvh, kvbT, kvh, vTh, KVLORA);
    // all-fp16 causal flash attention (q-RoPE in-kernel) -> attnh
    flash_h_kernel<<<dim3(S_LEN/BR, BATCH*NH), 256, FLASH_SMEM>>>(qh, kvh, vTh, kpeh, attnh);
    // out = attn @ o_w  [4096,2048] k=2048 (fp32 out)
    h16_gemm<float><<<dim3(HIDDEN/128, NROWS/128), 256, H_SMEM>>>(
        attnh, owT, out, NROWS, HIDDEN, ATTN_LD, HIDDEN, (float*)nullptr, 0, 1<<30);
}